// round 1
// baseline (speedup 1.0000x reference)
#include <cuda_runtime.h>
#include <math.h>

#define BB 8
#define CC 64
#define NCC 128
#define HH 192
#define WW 384
#define HWS (HH*WW)                 // 73728
#define ATT_SCALE 0.08838834764831845f   // 1/sqrt(128)

// ---------------- scratch (device globals; no runtime allocation) ----------------
// each is 8*128*73728 floats = 302 MB; norm buffers are 151 MB
__device__ float g_norm_l[BB*CC*HWS];
__device__ float g_norm_r[BB*CC*HWS];
__device__ float g_T0[BB*NCC*HWS];   // pre-dw V_l  -> later reused as S (2*1024*192*192 floats, same size)
__device__ float g_T1[BB*NCC*HWS];   // pre-dw K_l  -> later reused as O_l
__device__ float g_T2[BB*NCC*HWS];   // pre-dw Q    -> later reused as O_r
__device__ float g_T3[BB*NCC*HWS];   // pre-dw K_r
__device__ float g_T4[BB*NCC*HWS];   // pre-dw V_r
__device__ float g_Vl[BB*NCC*HWS];
__device__ float g_Kl[BB*NCC*HWS];
__device__ float g_Qm[BB*NCC*HWS];
__device__ float g_Kr[BB*NCC*HWS];
__device__ float g_Vr[BB*NCC*HWS];

// ---------------- LayerNorm2d (over channel dim, per pixel) ----------------
__global__ __launch_bounds__(256) void ln_kernel(
    const float* __restrict__ x, const float* __restrict__ gam,
    const float* __restrict__ bet, float* __restrict__ out) {
  int idx = blockIdx.x*256 + threadIdx.x;       // over B*HW
  int b = idx / HWS, p = idx % HWS;
  const float* xp = x + (size_t)b*CC*HWS + p;
  float v[CC];
  float s = 0.f;
#pragma unroll
  for (int c=0;c<CC;c++){ v[c]=xp[(size_t)c*HWS]; s+=v[c]; }
  float mu = s*(1.f/CC);
  float q=0.f;
#pragma unroll
  for (int c=0;c<CC;c++){ float d=v[c]-mu; q+=d*d; }
  float rstd = rsqrtf(q*(1.f/CC)+1e-6f);
  float* op = out + (size_t)b*CC*HWS + p;
#pragma unroll
  for (int c=0;c<CC;c++)
    op[(size_t)c*HWS] = (v[c]-mu)*rstd*__ldg(&gam[c]) + __ldg(&bet[c]);
}

// ---------------- generic 1x1 conv as GEMM: out[O, px] = W[O,K] @ in[K, px] ----------------
// tile: COUT x 128 pixels, 256 threads, per-thread (COUT/16) x 8 register tile, k-chunk 32
template<int COUT, int KDIM, bool DUAL, bool RES>
__global__ __launch_bounds__(256) void conv1x1_kernel(
    const float* __restrict__ inA, const float* __restrict__ inB,
    const float* __restrict__ w, const float* __restrict__ bias,
    const float* __restrict__ res, float* __restrict__ out) {
  __shared__ float sW[32][COUT+1];
  __shared__ float sX[32][128];
  int b = blockIdx.z;
  int p0 = blockIdx.x * 128;
  int t = threadIdx.x;
  int tx = t & 15, ty = t >> 4;
  constexpr int MR = COUT/16;
  float acc[MR][8];
#pragma unroll
  for (int i=0;i<MR;i++)
#pragma unroll
    for (int j=0;j<8;j++) acc[i][j]=0.f;

  for (int kb=0; kb<KDIM; kb+=32) {
#pragma unroll
    for (int r=0;r<16;r++) {                     // 32*128 elems / 256 thr
      int idx = t + 256*r;
      int pix = idx & 127, k = idx >> 7;
      int kg = kb + k;
      const float* src; int ch;
      if (DUAL) { src = (kg < CC) ? inA : inB; ch = kg & (CC-1); }
      else      { src = inA; ch = kg; }
      size_t chb = DUAL ? ((size_t)b*CC + ch) : ((size_t)b*KDIM + ch);
      sX[k][pix] = src[chb*HWS + p0 + pix];
    }
#pragma unroll
    for (int r=0;r<(32*COUT)/256;r++) {
      int idx = t + 256*r;
      int k = idx & 31, o = idx >> 5;
      sW[k][o] = w[(size_t)o*KDIM + kb + k];
    }
    __syncthreads();
#pragma unroll
    for (int k=0;k<32;k++) {
      float xv[8], wv[MR];
#pragma unroll
      for (int j=0;j<8;j++) xv[j]=sX[k][tx+16*j];
#pragma unroll
      for (int i=0;i<MR;i++) wv[i]=sW[k][ty+16*i];
#pragma unroll
      for (int i=0;i<MR;i++)
#pragma unroll
        for (int j=0;j<8;j++) acc[i][j] += wv[i]*xv[j];
    }
    __syncthreads();
  }
#pragma unroll
  for (int i=0;i<MR;i++) {
    int row = ty + 16*i;
    float bv = __ldg(&bias[row]);
    size_t obase = ((size_t)b*COUT + row)*HWS + p0;
#pragma unroll
    for (int j=0;j<8;j++) {
      int pix = tx + 16*j;
      float vv = acc[i][j] + bv;
      if (RES) vv += res[obase + pix];
      out[obase + pix] = vv;
    }
  }
}

// ---------------- depthwise 3x3 conv, SAME zero padding ----------------
__global__ __launch_bounds__(256) void dwconv_kernel(
    const float* __restrict__ in, const float* __restrict__ w,
    const float* __restrict__ bias, float* __restrict__ out) {
  size_t idx = (size_t)blockIdx.x*256 + threadIdx.x;  // over B*NC*HW
  size_t bc = idx / HWS;
  int p = (int)(idx % HWS);
  int c = (int)(bc % NCC);
  int h = p / WW, x = p - h*WW;
  const float* ip = in + bc*HWS;
  float acc = __ldg(&bias[c]);
#pragma unroll
  for (int dy=-1;dy<=1;dy++) {
    int hh = h+dy;
    if (hh<0||hh>=HH) continue;
#pragma unroll
    for (int dx=-1;dx<=1;dx++) {
      int xx = x+dx;
      if (xx<0||xx>=WW) continue;
      acc += ip[(size_t)hh*WW+xx]*__ldg(&w[c*9+(dy+1)*3+(dx+1)]);
    }
  }
  out[idx] = acc;
}

// ---------------- S = Q @ K^T * scale, batched over (side, b, c) ----------------
// M=N=192, K=384. side0: K_r (-> A_r2l for left output), side1: K_l
__global__ __launch_bounds__(256) void sgemm_nt_kernel() {
  __shared__ float sQ[32][65], sK[32][65];
  int bc = blockIdx.y, side = blockIdx.z;
  const float* qb = g_Qm + (size_t)bc*HWS;
  const float* km = (side==0 ? g_Kr : g_Kl) + (size_t)bc*HWS;
  int mt = blockIdx.x/3, nt = blockIdx.x%3;
  int m0 = mt*64, n0 = nt*64;
  int t = threadIdx.x, tx = t&15, ty = t>>4;
  float acc[4][4] = {};
  for (int kb=0;kb<WW;kb+=32) {
#pragma unroll
    for (int r=0;r<8;r++) {                      // 64*32/256
      int idx = t+256*r;
      int k = idx&31, m = idx>>5;
      sQ[k][m] = qb[(size_t)(m0+m)*WW + kb+k];
      sK[k][m] = km[(size_t)(n0+m)*WW + kb+k];
    }
    __syncthreads();
#pragma unroll
    for (int k=0;k<32;k++) {
      float qv[4], kv[4];
#pragma unroll
      for (int i=0;i<4;i++) qv[i]=sQ[k][ty+16*i];
#pragma unroll
      for (int j=0;j<4;j++) kv[j]=sK[k][tx+16*j];
#pragma unroll
      for (int i=0;i<4;i++)
#pragma unroll
        for (int j=0;j<4;j++) acc[i][j]+=qv[i]*kv[j];
    }
    __syncthreads();
  }
  float* sp = g_T0 + ((size_t)side*(BB*NCC) + bc)*(HH*HH);
#pragma unroll
  for (int i=0;i<4;i++)
#pragma unroll
    for (int j=0;j<4;j++)
      sp[(size_t)(m0+ty+16*i)*HH + n0+tx+16*j] = acc[i][j]*ATT_SCALE;
}

// ---------------- row softmax over 192 elems, in place in g_T0 ----------------
__global__ __launch_bounds__(256) void softmax_kernel() {
  size_t row = (size_t)blockIdx.x*8 + (threadIdx.x>>5);
  int lane = threadIdx.x&31;
  float* rp = g_T0 + row*HH;
  float v[6];
  float mx = -1e30f;
#pragma unroll
  for (int i=0;i<6;i++){ v[i]=rp[lane+32*i]; mx=fmaxf(mx,v[i]); }
#pragma unroll
  for (int o=16;o>0;o>>=1) mx = fmaxf(mx, __shfl_xor_sync(0xffffffffu, mx, o));
  float s=0.f;
#pragma unroll
  for (int i=0;i<6;i++){ v[i]=__expf(v[i]-mx); s+=v[i]; }
#pragma unroll
  for (int o=16;o>0;o>>=1) s += __shfl_xor_sync(0xffffffffu, s, o);
  float inv = 1.f/s;
#pragma unroll
  for (int i=0;i<6;i++) rp[lane+32*i]=v[i]*inv;
}

// ---------------- O = A @ V (NN), batched over (side, b, c) ----------------
// M=192, N=384, K=192. side0: V_l -> O_l(g_T1); side1: V_r -> O_r(g_T2)
__global__ __launch_bounds__(256) void ogemm_kernel() {
  __shared__ float sA[32][65];
  __shared__ float sV[32][64];
  int bc = blockIdx.y, side = blockIdx.z;
  const float* ab = g_T0 + ((size_t)side*(BB*NCC)+bc)*(HH*HH);
  const float* vb = (side==0 ? g_Vl : g_Vr) + (size_t)bc*HWS;
  float* ob = (side==0 ? g_T1 : g_T2) + (size_t)bc*HWS;
  int mt = blockIdx.x/6, nt = blockIdx.x%6;
  int m0 = mt*64, n0 = nt*64;
  int t = threadIdx.x, tx=t&15, ty=t>>4;
  float acc[4][4]={};
  for (int kb=0;kb<HH;kb+=32) {
#pragma unroll
    for (int r=0;r<8;r++) {
      int idx=t+256*r;
      { int k=idx&31, m=idx>>5;
        sA[k][m]=ab[(size_t)(m0+m)*HH + kb+k]; }
      { int n=idx&63, k=idx>>6;
        sV[k][n]=vb[(size_t)(kb+k)*WW + n0+n]; }
    }
    __syncthreads();
#pragma unroll
    for (int k=0;k<32;k++) {
      float av[4], vv[4];
#pragma unroll
      for (int i=0;i<4;i++) av[i]=sA[k][ty+16*i];
#pragma unroll
      for (int j=0;j<4;j++) vv[j]=sV[k][tx+16*j];
#pragma unroll
      for (int i=0;i<4;i++)
#pragma unroll
        for (int j=0;j<4;j++) acc[i][j]+=av[i]*vv[j];
    }
    __syncthreads();
  }
#pragma unroll
  for (int i=0;i<4;i++)
#pragma unroll
    for (int j=0;j<4;j++)
      ob[(size_t)(m0+ty+16*i)*WW + n0+tx+16*j]=acc[i][j];
}

// ---------------- launch ----------------
extern "C" void kernel_launch(void* const* d_in, const int* in_sizes, int n_in,
                              void* d_out, int out_size) {
  const float* x_l  = (const float*)d_in[0];
  const float* x_r  = (const float*)d_in[1];
  const float* ln1_g=(const float*)d_in[2];  const float* ln1_b=(const float*)d_in[3];
  const float* ln2_g=(const float*)d_in[4];  const float* ln2_b=(const float*)d_in[5];
  const float* w1=(const float*)d_in[6];   const float* b1=(const float*)d_in[7];
  const float* w2=(const float*)d_in[8];   const float* b2=(const float*)d_in[9];
  const float* w3=(const float*)d_in[10];  const float* b3=(const float*)d_in[11];
  const float* w4=(const float*)d_in[12];  const float* b4=(const float*)d_in[13];
  const float* w5=(const float*)d_in[14];  const float* b5=(const float*)d_in[15];
  const float* dw1=(const float*)d_in[16]; const float* db1=(const float*)d_in[17];
  const float* dw2=(const float*)d_in[18]; const float* db2=(const float*)d_in[19];
  const float* dw3=(const float*)d_in[20]; const float* db3=(const float*)d_in[21];
  const float* dw4=(const float*)d_in[22]; const float* db4=(const float*)d_in[23];
  const float* dw5=(const float*)d_in[24]; const float* db5=(const float*)d_in[25];
  const float* w6=(const float*)d_in[26];  const float* b6=(const float*)d_in[27];
  const float* w7=(const float*)d_in[28];  const float* b7=(const float*)d_in[29];
  float* out = (float*)d_out;

  float *norm_l,*norm_r,*T0,*T1,*T2,*T3,*T4,*Vl,*Kl,*Qm,*Kr,*Vr;
  cudaGetSymbolAddress((void**)&norm_l, g_norm_l);
  cudaGetSymbolAddress((void**)&norm_r, g_norm_r);
  cudaGetSymbolAddress((void**)&T0, g_T0);
  cudaGetSymbolAddress((void**)&T1, g_T1);
  cudaGetSymbolAddress((void**)&T2, g_T2);
  cudaGetSymbolAddress((void**)&T3, g_T3);
  cudaGetSymbolAddress((void**)&T4, g_T4);
  cudaGetSymbolAddress((void**)&Vl, g_Vl);
  cudaGetSymbolAddress((void**)&Kl, g_Kl);
  cudaGetSymbolAddress((void**)&Qm, g_Qm);
  cudaGetSymbolAddress((void**)&Kr, g_Kr);
  cudaGetSymbolAddress((void**)&Vr, g_Vr);

  // 1. LayerNorm2d
  ln_kernel<<<BB*HWS/256, 256>>>(x_l, ln1_g, ln1_b, norm_l);
  ln_kernel<<<BB*HWS/256, 256>>>(x_r, ln2_g, ln2_b, norm_r);

  // 2. five conv1x1 branches
  dim3 gconv(HWS/128, 1, BB);
  conv1x1_kernel<NCC,CC,false,false><<<gconv,256>>>(norm_l,nullptr,w1,b1,nullptr,T0);
  conv1x1_kernel<NCC,CC,false,false><<<gconv,256>>>(norm_l,nullptr,w2,b2,nullptr,T1);
  conv1x1_kernel<NCC,2*CC,true,false><<<gconv,256>>>(norm_l,norm_r,w3,b3,nullptr,T2);
  conv1x1_kernel<NCC,CC,false,false><<<gconv,256>>>(norm_r,nullptr,w4,b4,nullptr,T3);
  conv1x1_kernel<NCC,CC,false,false><<<gconv,256>>>(norm_r,nullptr,w5,b5,nullptr,T4);

  // 3. five depthwise 3x3 convs
  int dwblocks = BB*NCC*HWS/256;
  dwconv_kernel<<<dwblocks,256>>>(T0,dw1,db1,Vl);
  dwconv_kernel<<<dwblocks,256>>>(T1,dw2,db2,Kl);
  dwconv_kernel<<<dwblocks,256>>>(T2,dw3,db3,Qm);
  dwconv_kernel<<<dwblocks,256>>>(T3,dw4,db4,Kr);
  dwconv_kernel<<<dwblocks,256>>>(T4,dw5,db5,Vr);

  // 4. scores (writes into T0, now free), 5. softmax in place, 6. O = A@V (into T1/T2)
  sgemm_nt_kernel<<<dim3(9, BB*NCC, 2), 256>>>();
  softmax_kernel<<<(2*BB*NCC*HH)/8, 256>>>();
  ogemm_kernel<<<dim3(18, BB*NCC, 2), 256>>>();

  // 7. final conv1x1 + residual, write both halves of d_out
  conv1x1_kernel<CC,NCC,false,true><<<gconv,256>>>(T1,nullptr,w6,b6,x_l,out);
  conv1x1_kernel<CC,NCC,false,true><<<gconv,256>>>(T2,nullptr,w7,b7,x_r,out + (size_t)BB*CC*HWS);
}

// round 8
// speedup vs baseline: 1.5762x; 1.5762x over previous
#include <cuda_runtime.h>
#include <cuda_bf16.h>
#include <math.h>
#include <stdint.h>

constexpr int kB  = 8;
constexpr int kC  = 64;
constexpr int kNC = 128;
constexpr int kH  = 192;
constexpr int kW  = 384;
constexpr int kHW = kH * kW;                    // 73728
constexpr float kScale = 0.08838834764831845f;  // 1/sqrt(128)

// ---------------- scratch (device globals; no runtime allocation) ----------------
__device__ float g_norm_l[kB*kC*kHW];
__device__ float g_norm_r[kB*kC*kHW];
__device__ float g_T0[kB*kNC*kHW];   // pre-dw V_l -> reused as fp32 S (same byte size)
__device__ float g_T1[kB*kNC*kHW];   // pre-dw K_l -> reused as O_l
__device__ float g_T2[kB*kNC*kHW];   // pre-dw Q   -> reused as O_r
__device__ float g_T3[kB*kNC*kHW];   // pre-dw K_r
__device__ float g_T4[kB*kNC*kHW];   // pre-dw V_r
__device__ __nv_bfloat16 g_Vl[kB*kNC*kHW];
__device__ __nv_bfloat16 g_Kl[kB*kNC*kHW];
__device__ __nv_bfloat16 g_Qm[kB*kNC*kHW];
__device__ __nv_bfloat16 g_Kr[kB*kNC*kHW];
__device__ __nv_bfloat16 g_Vr[kB*kNC*kHW];
__device__ __nv_bfloat16 g_Abf[2ll*kB*kNC*kH*kH];  // bf16 softmaxed attention

// ---------------- mma helpers ----------------
__device__ __forceinline__ void ldsm4(uint32_t* r, uint32_t addr) {
  asm volatile("ldmatrix.sync.aligned.m8n8.x4.shared.b16 {%0,%1,%2,%3}, [%4];"
    : "=r"(r[0]), "=r"(r[1]), "=r"(r[2]), "=r"(r[3]) : "r"(addr));
}
__device__ __forceinline__ void ldsm4t(uint32_t* r, uint32_t addr) {
  asm volatile("ldmatrix.sync.aligned.m8n8.x4.trans.shared.b16 {%0,%1,%2,%3}, [%4];"
    : "=r"(r[0]), "=r"(r[1]), "=r"(r[2]), "=r"(r[3]) : "r"(addr));
}
__device__ __forceinline__ void mma16816(float* c, const uint32_t* a, uint32_t b0, uint32_t b1) {
  asm volatile("mma.sync.aligned.m16n8k16.row.col.f32.bf16.bf16.f32 "
    "{%0,%1,%2,%3}, {%4,%5,%6,%7}, {%8,%9}, {%0,%1,%2,%3};"
    : "+f"(c[0]), "+f"(c[1]), "+f"(c[2]), "+f"(c[3])
    : "r"(a[0]), "r"(a[1]), "r"(a[2]), "r"(a[3]), "r"(b0), "r"(b1));
}

// ---------------- LayerNorm2d (over channels, per pixel) ----------------
__global__ __launch_bounds__(256) void ln_kernel(
    const float* __restrict__ x, const float* __restrict__ gam,
    const float* __restrict__ bet, float* __restrict__ out) {
  int idx = blockIdx.x * 256 + threadIdx.x;     // over B*HW
  int b = idx / kHW, p = idx % kHW;
  const float* xp = x + (size_t)b*kC*kHW + p;
  float v[kC];
  float s = 0.f;
#pragma unroll
  for (int c = 0; c < kC; c++) { v[c] = xp[(size_t)c*kHW]; s += v[c]; }
  float mu = s * (1.f/kC);
  float q = 0.f;
#pragma unroll
  for (int c = 0; c < kC; c++) { float d = v[c]-mu; q += d*d; }
  float rstd = rsqrtf(q*(1.f/kC) + 1e-6f);
  float* op = out + (size_t)b*kC*kHW + p;
#pragma unroll
  for (int c = 0; c < kC; c++)
    op[(size_t)c*kHW] = (v[c]-mu)*rstd*__ldg(&gam[c]) + __ldg(&bet[c]);
}

// ---------------- conv1x1 as GEMM: out[O,px] = W[O,K] @ in[K,px] ----------------
template<int COUT, int KDIM, bool DUAL, bool RES>
__global__ __launch_bounds__(256) void conv1x1_kernel(
    const float* __restrict__ inA, const float* __restrict__ inB,
    const float* __restrict__ w, const float* __restrict__ bias,
    const float* __restrict__ res, float* __restrict__ out) {
  __shared__ float sW[32][COUT+1];
  __shared__ float sX[32][128];
  int b  = blockIdx.z;
  int p0 = blockIdx.x * 128;
  int t  = threadIdx.x;
  int tx = t & 15, ty = t >> 4;
  const int MR = COUT/16;
  float acc[COUT/16][8];
#pragma unroll
  for (int i = 0; i < MR; i++)
#pragma unroll
    for (int j = 0; j < 8; j++) acc[i][j] = 0.f;

  for (int kb = 0; kb < KDIM; kb += 32) {
#pragma unroll
    for (int r = 0; r < 16; r++) {               // 32*128 elems / 256 thr
      int idx = t + 256*r;
      int pix = idx & 127, k = idx >> 7;
      int kg = kb + k;
      const float* src; int ch;
      if (DUAL) { src = (kg < kC) ? inA : inB; ch = kg & (kC-1); }
      else      { src = inA; ch = kg; }
      size_t chb = DUAL ? ((size_t)b*kC + ch) : ((size_t)b*KDIM + ch);
      sX[k][pix] = src[chb*kHW + p0 + pix];
    }
#pragma unroll
    for (int r = 0; r < (32*COUT)/256; r++) {
      int idx = t + 256*r;
      int k = idx & 31, o = idx >> 5;
      sW[k][o] = w[(size_t)o*KDIM + kb + k];
    }
    __syncthreads();
#pragma unroll
    for (int k = 0; k < 32; k++) {
      float xv[8], wv[COUT/16];
#pragma unroll
      for (int j = 0; j < 8; j++) xv[j] = sX[k][tx + 16*j];
#pragma unroll
      for (int i = 0; i < MR; i++) wv[i] = sW[k][ty + 16*i];
#pragma unroll
      for (int i = 0; i < MR; i++)
#pragma unroll
        for (int j = 0; j < 8; j++) acc[i][j] += wv[i]*xv[j];
    }
    __syncthreads();
  }
#pragma unroll
  for (int i = 0; i < MR; i++) {
    int row = ty + 16*i;
    float bv = __ldg(&bias[row]);
    size_t obase = ((size_t)b*COUT + row)*kHW + p0;
#pragma unroll
    for (int j = 0; j < 8; j++) {
      int pix = tx + 16*j;
      float vv = acc[i][j] + bv;
      if (RES) vv += res[obase + pix];
      out[obase + pix] = vv;
    }
  }
}

// ---------------- depthwise 3x3, SAME zero padding, bf16 output ----------------
__global__ __launch_bounds__(256) void dwconv_kernel(
    const float* __restrict__ in, const float* __restrict__ w,
    const float* __restrict__ bias, __nv_bfloat16* __restrict__ out) {
  size_t idx = (size_t)blockIdx.x*256 + threadIdx.x;   // over B*NC*HW
  size_t bc = idx / kHW;
  int p = (int)(idx % kHW);
  int c = (int)(bc % kNC);
  int h = p / kW, x = p - h*kW;
  const float* ip = in + bc*kHW;
  float acc = __ldg(&bias[c]);
#pragma unroll
  for (int dy = -1; dy <= 1; dy++) {
    int hh = h + dy;
    if (hh < 0 || hh >= kH) continue;
#pragma unroll
    for (int dx = -1; dx <= 1; dx++) {
      int xx = x + dx;
      if (xx < 0 || xx >= kW) continue;
      acc += ip[(size_t)hh*kW + xx] * __ldg(&w[c*9 + (dy+1)*3 + (dx+1)]);
    }
  }
  out[idx] = __float2bfloat16(acc);
}

// ---------------- S = Q @ K^T (bf16 HMMA, fp32 S out, unscaled) ----------------
// M=N=192, K=384 per (side,bc). 64x64 block tile, 4 warps 2x2, warp 32x32.
__global__ __launch_bounds__(128) void sgemm_bf16_kernel() {
  __shared__ __nv_bfloat16 sQ[64*40];
  __shared__ __nv_bfloat16 sK[64*40];
  int bc = blockIdx.y, side = blockIdx.z;
  const __nv_bfloat16* qb = g_Qm + (size_t)bc*kHW;
  const __nv_bfloat16* km = (side == 0 ? g_Kr : g_Kl) + (size_t)bc*kHW;
  int mt = blockIdx.x / 3, nt = blockIdx.x % 3;
  int m0 = mt*64, n0 = nt*64;
  int t = threadIdx.x, warp = t >> 5, lane = t & 31;
  int wm = warp >> 1, wn = warp & 1;
  float acc[2][4][4];
#pragma unroll
  for (int i = 0; i < 2; i++)
#pragma unroll
    for (int j = 0; j < 4; j++)
#pragma unroll
      for (int k = 0; k < 4; k++) acc[i][j][k] = 0.f;

  uint32_t sQb = (uint32_t)__cvta_generic_to_shared(sQ);
  uint32_t sKb = (uint32_t)__cvta_generic_to_shared(sK);

  for (int kb = 0; kb < kW; kb += 32) {
#pragma unroll
    for (int r = 0; r < 2; r++) {
      int chunk = t + 128*r;                 // 256 chunks of 8 bf16 each per buffer
      int row = chunk >> 2, cg = chunk & 3;
      *(uint4*)(sQ + row*40 + cg*8) = *(const uint4*)(qb + (size_t)(m0+row)*kW + kb + cg*8);
      *(uint4*)(sK + row*40 + cg*8) = *(const uint4*)(km + (size_t)(n0+row)*kW + kb + cg*8);
    }
    __syncthreads();
#pragma unroll
    for (int ks = 0; ks < 2; ks++) {
      int k0 = ks*16;
      uint32_t a[2][4], b[2][4];
#pragma unroll
      for (int mf = 0; mf < 2; mf++) {
        int row = wm*32 + mf*16 + (lane & 15);
        int col = k0 + (lane >> 4)*8;
        ldsm4(a[mf], sQb + (uint32_t)(row*40 + col)*2);
      }
#pragma unroll
      for (int nb = 0; nb < 2; nb++) {
        int nrow = wn*32 + nb*16 + (lane >> 4)*8 + (lane & 7);
        int col  = k0 + ((lane >> 3) & 1)*8;
        ldsm4(b[nb], sKb + (uint32_t)(nrow*40 + col)*2);
      }
#pragma unroll
      for (int mf = 0; mf < 2; mf++)
#pragma unroll
        for (int nf = 0; nf < 4; nf++)
          mma16816(acc[mf][nf], a[mf], b[nf>>1][(nf&1)*2], b[nf>>1][(nf&1)*2+1]);
    }
    __syncthreads();
  }
  float* sp = g_T0 + ((size_t)side*(kB*kNC) + bc)*((size_t)kH*kH);
#pragma unroll
  for (int mf = 0; mf < 2; mf++)
#pragma unroll
    for (int nf = 0; nf < 4; nf++) {
      int r = m0 + wm*32 + mf*16 + (lane >> 2);
      int c = n0 + wn*32 + nf*8 + (lane & 3)*2;
      *(float2*)(sp + (size_t)r*kH + c)     = make_float2(acc[mf][nf][0], acc[mf][nf][1]);
      *(float2*)(sp + (size_t)(r+8)*kH + c) = make_float2(acc[mf][nf][2], acc[mf][nf][3]);
    }
}

// ---------------- row softmax over 192 (scale fused; fp32 in, bf16 out) ----------------
__global__ __launch_bounds__(256) void softmax_kernel() {
  size_t row = (size_t)blockIdx.x*8 + (threadIdx.x >> 5);
  int lane = threadIdx.x & 31;
  const float* rp = g_T0 + row*kH;
  __nv_bfloat16* op = g_Abf + row*kH;
  float v[6];
  float mx = -1e30f;
#pragma unroll
  for (int i = 0; i < 6; i++) { v[i] = rp[lane + 32*i]*kScale; mx = fmaxf(mx, v[i]); }
#pragma unroll
  for (int o = 16; o > 0; o >>= 1) mx = fmaxf(mx, __shfl_xor_sync(0xffffffffu, mx, o));
  float s = 0.f;
#pragma unroll
  for (int i = 0; i < 6; i++) { v[i] = __expf(v[i]-mx); s += v[i]; }
#pragma unroll
  for (int o = 16; o > 0; o >>= 1) s += __shfl_xor_sync(0xffffffffu, s, o);
  float inv = 1.f/s;
#pragma unroll
  for (int i = 0; i < 6; i++) op[lane + 32*i] = __float2bfloat16(v[i]*inv);
}

// ---------------- O = A @ V (bf16 HMMA, NN, fp32 out) ----------------
// M=192, N=384, K=192. 64x64 tile, 4 warps 2x2.
__global__ __launch_bounds__(128) void ogemm_bf16_kernel() {
  __shared__ __nv_bfloat16 sA[64*40];
  __shared__ __nv_bfloat16 sV[32*72];
  int bc = blockIdx.y, side = blockIdx.z;
  const __nv_bfloat16* ab = g_Abf + ((size_t)side*(kB*kNC) + bc)*((size_t)kH*kH);
  const __nv_bfloat16* vb = (side == 0 ? g_Vl : g_Vr) + (size_t)bc*kHW;
  float* ob = (side == 0 ? g_T1 : g_T2) + (size_t)bc*kHW;
  int mt = blockIdx.x / 6, nt = blockIdx.x % 6;
  int m0 = mt*64, n0 = nt*64;
  int t = threadIdx.x, warp = t >> 5, lane = t & 31;
  int wm = warp >> 1, wn = warp & 1;
  float acc[2][4][4];
#pragma unroll
  for (int i = 0; i < 2; i++)
#pragma unroll
    for (int j = 0; j < 4; j++)
#pragma unroll
      for (int k = 0; k < 4; k++) acc[i][j][k] = 0.f;

  uint32_t sAb = (uint32_t)__cvta_generic_to_shared(sA);
  uint32_t sVb = (uint32_t)__cvta_generic_to_shared(sV);

  for (int kb = 0; kb < kH; kb += 32) {
#pragma unroll
    for (int r = 0; r < 2; r++) {
      int chunk = t + 128*r;
      {
        int row = chunk >> 2, cg = chunk & 3;      // A: 64 rows x 32 cols
        *(uint4*)(sA + row*40 + cg*8) = *(const uint4*)(ab + (size_t)(m0+row)*kH + kb + cg*8);
      }
      {
        int row = chunk >> 3, cg = chunk & 7;      // V: 32 rows x 64 cols
        *(uint4*)(sV + row*72 + cg*8) = *(const uint4*)(vb + (size_t)(kb+row)*kW + n0 + cg*8);
      }
    }
    __syncthreads();
#pragma unroll
    for (int ks = 0; ks < 2; ks++) {
      int k0 = ks*16;
      uint32_t a[2][4], b[2][4];
#pragma unroll
      for (int mf = 0; mf < 2; mf++) {
        int row = wm*32 + mf*16 + (lane & 15);
        int col = k0 + (lane >> 4)*8;
        ldsm4(a[mf], sAb + (uint32_t)(row*40 + col)*2);
      }
#pragma unroll
      for (int nb = 0; nb < 2; nb++) {
        int krow = k0 + ((lane >> 3) & 1)*8 + (lane & 7);
        int ncol = wn*32 + nb*16 + (lane >> 4)*8;
        ldsm4t(b[nb], sVb + (uint32_t)(krow*72 + ncol)*2);
      }
#pragma unroll
      for (int mf = 0; mf < 2; mf++)
#pragma unroll
        for (int nf = 0; nf < 4; nf++)
          mma16816(acc[mf][nf], a[mf], b[nf>>1][(nf&1)*2], b[nf>>1][(nf&1)*2+1]);
    }
    __syncthreads();
  }
#pragma unroll
  for (int mf = 0; mf < 2; mf++)
#pragma unroll
    for (int nf = 0; nf < 4; nf++) {
      int r = m0 + wm*32 + mf*16 + (lane >> 2);
      int c = n0 + wn*32 + nf*8 + (lane & 3)*2;
      *(float2*)(ob + (size_t)r*kW + c)     = make_float2(acc[mf][nf][0], acc[mf][nf][1]);
      *(float2*)(ob + (size_t)(r+8)*kW + c) = make_float2(acc[mf][nf][2], acc[mf][nf][3]);
    }
}

// ---------------- launch ----------------
extern "C" void kernel_launch(void* const* d_in, const int* in_sizes, int n_in,
                              void* d_out, int out_size) {
  const float* x_l   = (const float*)d_in[0];
  const float* x_r   = (const float*)d_in[1];
  const float* ln1_g = (const float*)d_in[2];
  const float* ln1_b = (const float*)d_in[3];
  const float* ln2_g = (const float*)d_in[4];
  const float* ln2_b = (const float*)d_in[5];
  const float* w1 = (const float*)d_in[6];   const float* b1 = (const float*)d_in[7];
  const float* w2 = (const float*)d_in[8];   const float* b2 = (const float*)d_in[9];
  const float* w3 = (const float*)d_in[10];  const float* b3 = (const float*)d_in[11];
  const float* w4 = (const float*)d_in[12];  const float* b4 = (const float*)d_in[13];
  const float* w5 = (const float*)d_in[14];  const float* b5 = (const float*)d_in[15];
  const float* dw1 = (const float*)d_in[16]; const float* db1 = (const float*)d_in[17];
  const float* dw2 = (const float*)d_in[18]; const float* db2 = (const float*)d_in[19];
  const float* dw3 = (const float*)d_in[20]; const float* db3 = (const float*)d_in[21];
  const float* dw4 = (const float*)d_in[22]; const float* db4 = (const float*)d_in[23];
  const float* dw5 = (const float*)d_in[24]; const float* db5 = (const float*)d_in[25];
  const float* w6 = (const float*)d_in[26];  const float* b6 = (const float*)d_in[27];
  const float* w7 = (const float*)d_in[28];  const float* b7 = (const float*)d_in[29];
  float* out = (float*)d_out;

  float *norm_l, *norm_r, *T0, *T1, *T2, *T3, *T4;
  __nv_bfloat16 *Vl, *Kl, *Qm, *Kr, *Vr;
  cudaGetSymbolAddress((void**)&norm_l, g_norm_l);
  cudaGetSymbolAddress((void**)&norm_r, g_norm_r);
  cudaGetSymbolAddress((void**)&T0, g_T0);
  cudaGetSymbolAddress((void**)&T1, g_T1);
  cudaGetSymbolAddress((void**)&T2, g_T2);
  cudaGetSymbolAddress((void**)&T3, g_T3);
  cudaGetSymbolAddress((void**)&T4, g_T4);
  cudaGetSymbolAddress((void**)&Vl, g_Vl);
  cudaGetSymbolAddress((void**)&Kl, g_Kl);
  cudaGetSymbolAddress((void**)&Qm, g_Qm);
  cudaGetSymbolAddress((void**)&Kr, g_Kr);
  cudaGetSymbolAddress((void**)&Vr, g_Vr);

  // 1. LayerNorm2d
  ln_kernel<<<kB*kHW/256, 256>>>(x_l, ln1_g, ln1_b, norm_l);
  ln_kernel<<<kB*kHW/256, 256>>>(x_r, ln2_g, ln2_b, norm_r);

  // 2. five conv1x1 branches
  dim3 gconv(kHW/128, 1, kB);
  conv1x1_kernel<kNC, kC, false, false><<<gconv, 256>>>(norm_l, nullptr, w1, b1, nullptr, T0);
  conv1x1_kernel<kNC, kC, false, false><<<gconv, 256>>>(norm_l, nullptr, w2, b2, nullptr, T1);
  conv1x1_kernel<kNC, 2*kC, true, false><<<gconv, 256>>>(norm_l, norm_r, w3, b3, nullptr, T2);
  conv1x1_kernel<kNC, kC, false, false><<<gconv, 256>>>(norm_r, nullptr, w4, b4, nullptr, T3);
  conv1x1_kernel<kNC, kC, false, false><<<gconv, 256>>>(norm_r, nullptr, w5, b5, nullptr, T4);

  // 3. five depthwise 3x3 convs -> bf16 Q/K/V
  int dwblocks = kB*kNC*kHW/256;
  dwconv_kernel<<<dwblocks, 256>>>(T0, dw1, db1, Vl);
  dwconv_kernel<<<dwblocks, 256>>>(T1, dw2, db2, Kl);
  dwconv_kernel<<<dwblocks, 256>>>(T2, dw3, db3, Qm);
  dwconv_kernel<<<dwblocks, 256>>>(T3, dw4, db4, Kr);
  dwconv_kernel<<<dwblocks, 256>>>(T4, dw5, db5, Vr);

  // 4. tensor-core attention: S (into T0), softmax (T0 -> Abf), O = A@V (into T1/T2)
  sgemm_bf16_kernel<<<dim3(9, kB*kNC, 2), 128>>>();
  softmax_kernel<<<(2*kB*kNC*kH)/8, 256>>>();
  ogemm_bf16_kernel<<<dim3(18, kB*kNC, 2), 128>>>();

  // 5. final conv1x1 + residual, both halves of d_out
  conv1x1_kernel<kC, kNC, false, true><<<gconv, 256>>>(T1, nullptr, w6, b6, x_l, out);
  conv1x1_kernel<kC, kNC, false, true><<<gconv, 256>>>(T2, nullptr, w7, b7, x_r, out + (size_t)kB*kC*kHW);
}

// round 9
// speedup vs baseline: 2.3463x; 1.4886x over previous
#include <cuda_runtime.h>
#include <cuda_bf16.h>
#include <math.h>
#include <stdint.h>

constexpr int kB  = 8;
constexpr int kC  = 64;
constexpr int kNC = 128;
constexpr int kH  = 192;
constexpr int kW  = 384;
constexpr int kHW = kH * kW;                    // 73728
constexpr float kScale = 0.08838834764831845f;  // 1/sqrt(128)

// ---------------- scratch (device globals; no runtime allocation) ----------------
__device__ __nv_bfloat16 g_nl[kB*kC*kHW];
__device__ __nv_bfloat16 g_nr[kB*kC*kHW];
__device__ __nv_bfloat16 g_P0[kB*kNC*kHW];
__device__ __nv_bfloat16 g_P1[kB*kNC*kHW];
__device__ __nv_bfloat16 g_P2[kB*kNC*kHW];
__device__ __nv_bfloat16 g_P3[kB*kNC*kHW];
__device__ __nv_bfloat16 g_P4[kB*kNC*kHW];
__device__ __nv_bfloat16 g_Vl[kB*kNC*kHW];
__device__ __nv_bfloat16 g_Kl[kB*kNC*kHW];
__device__ __nv_bfloat16 g_Qm[kB*kNC*kHW];
__device__ __nv_bfloat16 g_Kr[kB*kNC*kHW];
__device__ __nv_bfloat16 g_Vr[kB*kNC*kHW];
__device__ __nv_bfloat16 g_Abf[2ll*kB*kNC*kH*kH];
__device__ __nv_bfloat16 g_Ol[kB*kNC*kHW];
__device__ __nv_bfloat16 g_Or[kB*kNC*kHW];

// ---------------- mma helpers ----------------
__device__ __forceinline__ void ldsm4(uint32_t* r, uint32_t addr) {
  asm volatile("ldmatrix.sync.aligned.m8n8.x4.shared.b16 {%0,%1,%2,%3}, [%4];"
    : "=r"(r[0]), "=r"(r[1]), "=r"(r[2]), "=r"(r[3]) : "r"(addr));
}
__device__ __forceinline__ void ldsm4t(uint32_t* r, uint32_t addr) {
  asm volatile("ldmatrix.sync.aligned.m8n8.x4.trans.shared.b16 {%0,%1,%2,%3}, [%4];"
    : "=r"(r[0]), "=r"(r[1]), "=r"(r[2]), "=r"(r[3]) : "r"(addr));
}
__device__ __forceinline__ void mma16816(float* c, const uint32_t* a, uint32_t b0, uint32_t b1) {
  asm volatile("mma.sync.aligned.m16n8k16.row.col.f32.bf16.bf16.f32 "
    "{%0,%1,%2,%3}, {%4,%5,%6,%7}, {%8,%9}, {%0,%1,%2,%3};"
    : "+f"(c[0]), "+f"(c[1]), "+f"(c[2]), "+f"(c[3])
    : "r"(a[0]), "r"(a[1]), "r"(a[2]), "r"(a[3]), "r"(b0), "r"(b1));
}
__device__ __forceinline__ __nv_bfloat162 pack_bf2(float a, float b) {
  return __floats2bfloat162_rn(a, b);
}

// ---------------- LayerNorm2d (over channels, per pixel), bf16 out ----------------
__global__ __launch_bounds__(256) void ln_kernel(
    const float* __restrict__ x, const float* __restrict__ gam,
    const float* __restrict__ bet, __nv_bfloat16* __restrict__ out) {
  int idx = blockIdx.x * 256 + threadIdx.x;     // over B*HW
  int b = idx / kHW, p = idx % kHW;
  const float* xp = x + (size_t)b*kC*kHW + p;
  float v[kC];
  float s = 0.f;
#pragma unroll
  for (int c = 0; c < kC; c++) { v[c] = xp[(size_t)c*kHW]; s += v[c]; }
  float mu = s * (1.f/kC);
  float q = 0.f;
#pragma unroll
  for (int c = 0; c < kC; c++) { float d = v[c]-mu; q += d*d; }
  float rstd = rsqrtf(q*(1.f/kC) + 1e-6f);
  __nv_bfloat16* op = out + (size_t)b*kC*kHW + p;
#pragma unroll
  for (int c = 0; c < kC; c++)
    op[(size_t)c*kHW] = __float2bfloat16((v[c]-mu)*rstd*__ldg(&gam[c]) + __ldg(&bet[c]));
}

// ---------------- conv1x1 as bf16 HMMA GEMM ----------------
// out[COUT, 128px] per block. 256 threads = 8 warps: (WM x WN), warp tile 64 x (128/WN).
// !RES: bf16 out. RES: fp32 out = acc + bias + res.
template<int COUT, int KDIM, bool DUAL, bool RES>
__global__ __launch_bounds__(256) void conv1x1_mma_kernel(
    const __nv_bfloat16* __restrict__ inA, const __nv_bfloat16* __restrict__ inB,
    const float* __restrict__ w, const float* __restrict__ bias,
    const float* __restrict__ res, float* __restrict__ outF,
    __nv_bfloat16* __restrict__ outB) {
  constexpr int WM = COUT/64;          // 2 (COUT=128) or 1 (COUT=64)
  constexpr int WN = 8/WM;             // 4 or 8
  constexpr int WNC = 128/WN;          // warp n-cols: 32 or 16
  constexpr int NF = WNC/8;            // 4 or 2
  constexpr int NB = NF/2 > 0 ? NF/2 : 1;  // 2 or 1
  constexpr int KP = KDIM + 8;
  __shared__ __nv_bfloat16 sW[COUT*KP];
  __shared__ __nv_bfloat16 sX[KDIM*136];

  int b  = blockIdx.z;
  int p0 = blockIdx.x * 128;
  int t  = threadIdx.x, warp = t >> 5, lane = t & 31;
  int wm = warp / WN, wn = warp % WN;

  // weights fp32 -> bf16 smem (row-major [COUT][KDIM])
  for (int idx = t; idx < COUT*KDIM; idx += 256) {
    int o = idx / KDIM, k = idx - o*KDIM;
    sW[o*KP + k] = __float2bfloat16(__ldg(&w[idx]));
  }
  // activations: sX[k][pix]
  for (int chunk = t; chunk < KDIM*16; chunk += 256) {
    int row = chunk >> 4, cg = chunk & 15;
    const __nv_bfloat16* src;
    if (DUAL) src = (row < kC) ? (inA + ((size_t)b*kC + row)*kHW)
                               : (inB + ((size_t)b*kC + (row-kC))*kHW);
    else      src = inA + ((size_t)b*KDIM + row)*kHW;
    *(uint4*)(sX + row*136 + cg*8) = *(const uint4*)(src + p0 + cg*8);
  }
  __syncthreads();

  float acc[4][NF][4];
#pragma unroll
  for (int i = 0; i < 4; i++)
#pragma unroll
    for (int j = 0; j < NF; j++)
#pragma unroll
      for (int k = 0; k < 4; k++) acc[i][j][k] = 0.f;

  uint32_t sWb = (uint32_t)__cvta_generic_to_shared(sW);
  uint32_t sXb = (uint32_t)__cvta_generic_to_shared(sX);

#pragma unroll
  for (int k0 = 0; k0 < KDIM; k0 += 16) {
    uint32_t a[4][4];
#pragma unroll
    for (int mf = 0; mf < 4; mf++) {
      int row = wm*64 + mf*16 + (lane & 15);
      int col = k0 + (lane >> 4)*8;
      ldsm4(a[mf], sWb + (uint32_t)(row*KP + col)*2);
    }
    uint32_t bfr[NB][4];
#pragma unroll
    for (int nb = 0; nb < NB; nb++) {
      int krow = k0 + ((lane >> 3) & 1)*8 + (lane & 7);
      int ncol = wn*WNC + nb*16 + (lane >> 4)*8;
      ldsm4t(bfr[nb], sXb + (uint32_t)(krow*136 + ncol)*2);
    }
#pragma unroll
    for (int mf = 0; mf < 4; mf++)
#pragma unroll
      for (int nf = 0; nf < NF; nf++)
        mma16816(acc[mf][nf], a[mf], bfr[nf>>1][(nf&1)*2], bfr[nf>>1][(nf&1)*2+1]);
  }

#pragma unroll
  for (int mf = 0; mf < 4; mf++) {
    int row = wm*64 + mf*16 + (lane >> 2);
    float bv0 = __ldg(&bias[row]);
    float bv1 = __ldg(&bias[row+8]);
#pragma unroll
    for (int nf = 0; nf < NF; nf++) {
      int col = wn*WNC + nf*8 + (lane & 3)*2;
      size_t o0 = ((size_t)b*COUT + row)*kHW + p0 + col;
      size_t o1 = o0 + (size_t)8*kHW;
      if (RES) {
        float2 r0 = *(const float2*)(res + o0);
        float2 r1 = *(const float2*)(res + o1);
        *(float2*)(outF + o0) = make_float2(acc[mf][nf][0]+bv0+r0.x, acc[mf][nf][1]+bv0+r0.y);
        *(float2*)(outF + o1) = make_float2(acc[mf][nf][2]+bv1+r1.x, acc[mf][nf][3]+bv1+r1.y);
      } else {
        *(__nv_bfloat162*)(outB + o0) = pack_bf2(acc[mf][nf][0]+bv0, acc[mf][nf][1]+bv0);
        *(__nv_bfloat162*)(outB + o1) = pack_bf2(acc[mf][nf][2]+bv1, acc[mf][nf][3]+bv1);
      }
    }
  }
}

// ---------------- depthwise 3x3, SAME zero padding, bf16 in/out ----------------
__global__ __launch_bounds__(256) void dwconv_kernel(
    const __nv_bfloat16* __restrict__ in, const float* __restrict__ w,
    const float* __restrict__ bias, __nv_bfloat16* __restrict__ out) {
  size_t idx = (size_t)blockIdx.x*256 + threadIdx.x;   // over B*NC*HW
  size_t bc = idx / kHW;
  int p = (int)(idx % kHW);
  int c = (int)(bc % kNC);
  int h = p / kW, x = p - h*kW;
  const __nv_bfloat16* ip = in + bc*kHW;
  float acc = __ldg(&bias[c]);
#pragma unroll
  for (int dy = -1; dy <= 1; dy++) {
    int hh = h + dy;
    if (hh < 0 || hh >= kH) continue;
#pragma unroll
    for (int dx = -1; dx <= 1; dx++) {
      int xx = x + dx;
      if (xx < 0 || xx >= kW) continue;
      acc += __bfloat162float(ip[(size_t)hh*kW + xx]) * __ldg(&w[c*9 + (dy+1)*3 + (dx+1)]);
    }
  }
  out[idx] = __float2bfloat16(acc);
}

// ---------------- fused S = softmax(Q K^T * scale): bf16 A out ----------------
// Block: M=64 rows x full N=192, K=384. 128 threads = 4 warps; warp = 16 rows x 192 cols.
__global__ __launch_bounds__(128) void sgemm_softmax_kernel() {
  __shared__ __nv_bfloat16 sQ[64*40];
  __shared__ __nv_bfloat16 sK[192*40];
  int bc = blockIdx.y, side = blockIdx.z;
  const __nv_bfloat16* qb = g_Qm + (size_t)bc*kHW;
  const __nv_bfloat16* km = (side == 0 ? g_Kr : g_Kl) + (size_t)bc*kHW;
  int m0 = blockIdx.x * 64;
  int t = threadIdx.x, warp = t >> 5, lane = t & 31;

  float acc[24][4];
#pragma unroll
  for (int i = 0; i < 24; i++)
#pragma unroll
    for (int j = 0; j < 4; j++) acc[i][j] = 0.f;

  uint32_t sQb = (uint32_t)__cvta_generic_to_shared(sQ);
  uint32_t sKb = (uint32_t)__cvta_generic_to_shared(sK);

  for (int kb = 0; kb < kW; kb += 32) {
#pragma unroll
    for (int chunk = t; chunk < 256; chunk += 128) {        // Q: 64 x 32
      int row = chunk >> 2, cg = chunk & 3;
      *(uint4*)(sQ + row*40 + cg*8) = *(const uint4*)(qb + (size_t)(m0+row)*kW + kb + cg*8);
    }
#pragma unroll
    for (int chunk = t; chunk < 768; chunk += 128) {        // K: 192 x 32
      int row = chunk >> 2, cg = chunk & 3;
      *(uint4*)(sK + row*40 + cg*8) = *(const uint4*)(km + (size_t)row*kW + kb + cg*8);
    }
    __syncthreads();
#pragma unroll
    for (int ks = 0; ks < 2; ks++) {
      int k0 = ks*16;
      uint32_t a[4];
      {
        int row = warp*16 + (lane & 15);
        int col = k0 + (lane >> 4)*8;
        ldsm4(a, sQb + (uint32_t)(row*40 + col)*2);
      }
      uint32_t bf[12][4];
#pragma unroll
      for (int nb = 0; nb < 12; nb++) {
        int nrow = nb*16 + (lane >> 4)*8 + (lane & 7);
        int col  = k0 + ((lane >> 3) & 1)*8;
        ldsm4(bf[nb], sKb + (uint32_t)(nrow*40 + col)*2);
      }
#pragma unroll
      for (int nf = 0; nf < 24; nf++)
        mma16816(acc[nf], a, bf[nf>>1][(nf&1)*2], bf[nf>>1][(nf&1)*2+1]);
    }
    __syncthreads();
  }

  // scale
#pragma unroll
  for (int nf = 0; nf < 24; nf++)
#pragma unroll
    for (int j = 0; j < 4; j++) acc[nf][j] *= kScale;

  // row softmax: lane holds rows r0=(lane>>2), r1=r0+8 of warp tile; cols spread over quad
  float mx0 = -1e30f, mx1 = -1e30f;
#pragma unroll
  for (int nf = 0; nf < 24; nf++) {
    mx0 = fmaxf(mx0, fmaxf(acc[nf][0], acc[nf][1]));
    mx1 = fmaxf(mx1, fmaxf(acc[nf][2], acc[nf][3]));
  }
#pragma unroll
  for (int o = 1; o <= 2; o <<= 1) {
    mx0 = fmaxf(mx0, __shfl_xor_sync(0xffffffffu, mx0, o));
    mx1 = fmaxf(mx1, __shfl_xor_sync(0xffffffffu, mx1, o));
  }
  float s0 = 0.f, s1 = 0.f;
#pragma unroll
  for (int nf = 0; nf < 24; nf++) {
    acc[nf][0] = __expf(acc[nf][0]-mx0); s0 += acc[nf][0];
    acc[nf][1] = __expf(acc[nf][1]-mx0); s0 += acc[nf][1];
    acc[nf][2] = __expf(acc[nf][2]-mx1); s1 += acc[nf][2];
    acc[nf][3] = __expf(acc[nf][3]-mx1); s1 += acc[nf][3];
  }
#pragma unroll
  for (int o = 1; o <= 2; o <<= 1) {
    s0 += __shfl_xor_sync(0xffffffffu, s0, o);
    s1 += __shfl_xor_sync(0xffffffffu, s1, o);
  }
  float i0 = 1.f/s0, i1 = 1.f/s1;

  __nv_bfloat16* ap = g_Abf + ((size_t)side*(kB*kNC) + bc)*((size_t)kH*kH);
  int r0 = m0 + warp*16 + (lane >> 2);
#pragma unroll
  for (int nf = 0; nf < 24; nf++) {
    int c = nf*8 + (lane & 3)*2;
    *(__nv_bfloat162*)(ap + (size_t)r0*kH + c)     = pack_bf2(acc[nf][0]*i0, acc[nf][1]*i0);
    *(__nv_bfloat162*)(ap + (size_t)(r0+8)*kH + c) = pack_bf2(acc[nf][2]*i1, acc[nf][3]*i1);
  }
}

// ---------------- O = A @ V (bf16 HMMA, NN, bf16 out) ----------------
// M=192, N=384, K=192. 64x64 tile, 4 warps 2x2.
__global__ __launch_bounds__(128) void ogemm_bf16_kernel() {
  __shared__ __nv_bfloat16 sA[64*40];
  __shared__ __nv_bfloat16 sV[32*72];
  int bc = blockIdx.y, side = blockIdx.z;
  const __nv_bfloat16* ab = g_Abf + ((size_t)side*(kB*kNC) + bc)*((size_t)kH*kH);
  const __nv_bfloat16* vb = (side == 0 ? g_Vl : g_Vr) + (size_t)bc*kHW;
  __nv_bfloat16* ob = (side == 0 ? g_Ol : g_Or) + (size_t)bc*kHW;
  int mt = blockIdx.x / 6, nt = blockIdx.x % 6;
  int m0 = mt*64, n0 = nt*64;
  int t = threadIdx.x, warp = t >> 5, lane = t & 31;
  int wm = warp >> 1, wn = warp & 1;
  float acc[2][4][4];
#pragma unroll
  for (int i = 0; i < 2; i++)
#pragma unroll
    for (int j = 0; j < 4; j++)
#pragma unroll
      for (int k = 0; k < 4; k++) acc[i][j][k] = 0.f;

  uint32_t sAb = (uint32_t)__cvta_generic_to_shared(sA);
  uint32_t sVb = (uint32_t)__cvta_generic_to_shared(sV);

  for (int kb = 0; kb < kH; kb += 32) {
#pragma unroll
    for (int r = 0; r < 2; r++) {
      int chunk = t + 128*r;
      {
        int row = chunk >> 2, cg = chunk & 3;      // A: 64 x 32
        *(uint4*)(sA + row*40 + cg*8) = *(const uint4*)(ab + (size_t)(m0+row)*kH + kb + cg*8);
      }
      {
        int row = chunk >> 3, cg = chunk & 7;      // V: 32 x 64
        *(uint4*)(sV + row*72 + cg*8) = *(const uint4*)(vb + (size_t)(kb+row)*kW + n0 + cg*8);
      }
    }
    __syncthreads();
#pragma unroll
    for (int ks = 0; ks < 2; ks++) {
      int k0 = ks*16;
      uint32_t a[2][4], b[2][4];
#pragma unroll
      for (int mf = 0; mf < 2; mf++) {
        int row = wm*32 + mf*16 + (lane & 15);
        int col = k0 + (lane >> 4)*8;
        ldsm4(a[mf], sAb + (uint32_t)(row*40 + col)*2);
      }
#pragma unroll
      for (int nb = 0; nb < 2; nb++) {
        int krow = k0 + ((lane >> 3) & 1)*8 + (lane & 7);
        int ncol = wn*32 + nb*16 + (lane >> 4)*8;
        ldsm4t(b[nb], sVb + (uint32_t)(krow*72 + ncol)*2);
      }
#pragma unroll
      for (int mf = 0; mf < 2; mf++)
#pragma unroll
        for (int nf = 0; nf < 4; nf++)
          mma16816(acc[mf][nf], a[mf], b[nf>>1][(nf&1)*2], b[nf>>1][(nf&1)*2+1]);
    }
    __syncthreads();
  }
#pragma unroll
  for (int mf = 0; mf < 2; mf++)
#pragma unroll
    for (int nf = 0; nf < 4; nf++) {
      int r = m0 + wm*32 + mf*16 + (lane >> 2);
      int c = n0 + wn*32 + nf*8 + (lane & 3)*2;
      *(__nv_bfloat162*)(ob + (size_t)r*kW + c)     = pack_bf2(acc[mf][nf][0], acc[mf][nf][1]);
      *(__nv_bfloat162*)(ob + (size_t)(r+8)*kW + c) = pack_bf2(acc[mf][nf][2], acc[mf][nf][3]);
    }
}

// ---------------- launch ----------------
extern "C" void kernel_launch(void* const* d_in, const int* in_sizes, int n_in,
                              void* d_out, int out_size) {
  const float* x_l   = (const float*)d_in[0];
  const float* x_r   = (const float*)d_in[1];
  const float* ln1_g = (const float*)d_in[2];
  const float* ln1_b = (const float*)d_in[3];
  const float* ln2_g = (const float*)d_in[4];
  const float* ln2_b = (const float*)d_in[5];
  const float* w1 = (const float*)d_in[6];   const float* b1 = (const float*)d_in[7];
  const float* w2 = (const float*)d_in[8];   const float* b2 = (const float*)d_in[9];
  const float* w3 = (const float*)d_in[10];  const float* b3 = (const float*)d_in[11];
  const float* w4 = (const float*)d_in[12];  const float* b4 = (const float*)d_in[13];
  const float* w5 = (const float*)d_in[14];  const float* b5 = (const float*)d_in[15];
  const float* dw1 = (const float*)d_in[16]; const float* db1 = (const float*)d_in[17];
  const float* dw2 = (const float*)d_in[18]; const float* db2 = (const float*)d_in[19];
  const float* dw3 = (const float*)d_in[20]; const float* db3 = (const float*)d_in[21];
  const float* dw4 = (const float*)d_in[22]; const float* db4 = (const float*)d_in[23];
  const float* dw5 = (const float*)d_in[24]; const float* db5 = (const float*)d_in[25];
  const float* w6 = (const float*)d_in[26];  const float* b6 = (const float*)d_in[27];
  const float* w7 = (const float*)d_in[28];  const float* b7 = (const float*)d_in[29];
  float* out = (float*)d_out;

  __nv_bfloat16 *nl, *nr, *P0, *P1, *P2, *P3, *P4, *Vl, *Kl, *Qm, *Kr, *Vr, *Ol, *Or;
  cudaGetSymbolAddress((void**)&nl, g_nl);
  cudaGetSymbolAddress((void**)&nr, g_nr);
  cudaGetSymbolAddress((void**)&P0, g_P0);
  cudaGetSymbolAddress((void**)&P1, g_P1);
  cudaGetSymbolAddress((void**)&P2, g_P2);
  cudaGetSymbolAddress((void**)&P3, g_P3);
  cudaGetSymbolAddress((void**)&P4, g_P4);
  cudaGetSymbolAddress((void**)&Vl, g_Vl);
  cudaGetSymbolAddress((void**)&Kl, g_Kl);
  cudaGetSymbolAddress((void**)&Qm, g_Qm);
  cudaGetSymbolAddress((void**)&Kr, g_Kr);
  cudaGetSymbolAddress((void**)&Vr, g_Vr);
  cudaGetSymbolAddress((void**)&Ol, g_Ol);
  cudaGetSymbolAddress((void**)&Or, g_Or);

  // 1. LayerNorm2d -> bf16
  ln_kernel<<<kB*kHW/256, 256>>>(x_l, ln1_g, ln1_b, nl);
  ln_kernel<<<kB*kHW/256, 256>>>(x_r, ln2_g, ln2_b, nr);

  // 2. five conv1x1 (bf16 HMMA) -> bf16 pre-dw tensors
  dim3 gconv(kHW/128, 1, kB);
  conv1x1_mma_kernel<kNC, kC, false, false><<<gconv, 256>>>(nl, nullptr, w1, b1, nullptr, nullptr, P0);
  conv1x1_mma_kernel<kNC, kC, false, false><<<gconv, 256>>>(nl, nullptr, w2, b2, nullptr, nullptr, P1);
  conv1x1_mma_kernel<kNC, 2*kC, true, false><<<gconv, 256>>>(nl, nr, w3, b3, nullptr, nullptr, P2);
  conv1x1_mma_kernel<kNC, kC, false, false><<<gconv, 256>>>(nr, nullptr, w4, b4, nullptr, nullptr, P3);
  conv1x1_mma_kernel<kNC, kC, false, false><<<gconv, 256>>>(nr, nullptr, w5, b5, nullptr, nullptr, P4);

  // 3. five depthwise 3x3 convs (bf16 -> bf16)
  int dwblocks = kB*kNC*kHW/256;
  dwconv_kernel<<<dwblocks, 256>>>(P0, dw1, db1, Vl);
  dwconv_kernel<<<dwblocks, 256>>>(P1, dw2, db2, Kl);
  dwconv_kernel<<<dwblocks, 256>>>(P2, dw3, db3, Qm);
  dwconv_kernel<<<dwblocks, 256>>>(P3, dw4, db4, Kr);
  dwconv_kernel<<<dwblocks, 256>>>(P4, dw5, db5, Vr);

  // 4. fused S-GEMM + softmax -> bf16 A; O = A @ V -> bf16 O
  sgemm_softmax_kernel<<<dim3(3, kB*kNC, 2), 128>>>();
  ogemm_bf16_kernel<<<dim3(18, kB*kNC, 2), 128>>>();

  // 5. final conv1x1 (bf16 HMMA) + residual, fp32 out
  conv1x1_mma_kernel<kC, kNC, false, true><<<gconv, 256>>>(Ol, nullptr, w6, b6, x_l, out, nullptr);
  conv1x1_mma_kernel<kC, kNC, false, true><<<gconv, 256>>>(Or, nullptr, w7, b7, x_r, out + (size_t)kB*kC*kHW, nullptr);
}

// round 10
// speedup vs baseline: 3.4658x; 1.4771x over previous
#include <cuda_runtime.h>
#include <cuda_bf16.h>
#include <math.h>
#include <stdint.h>

constexpr int kB  = 8;
constexpr int kC  = 64;
constexpr int kNC = 128;
constexpr int kH  = 192;
constexpr int kW  = 384;
constexpr int kHW = kH * kW;                    // 73728
constexpr float kScale = 0.08838834764831845f;  // 1/sqrt(128)

// ---------------- scratch (device globals; no runtime allocation) ----------------
__device__ __nv_bfloat16 g_nl[kB*kC*kHW];
__device__ __nv_bfloat16 g_nr[kB*kC*kHW];
__device__ __nv_bfloat16 g_P0[kB*kNC*kHW];
__device__ __nv_bfloat16 g_P1[kB*kNC*kHW];
__device__ __nv_bfloat16 g_P2[kB*kNC*kHW];
__device__ __nv_bfloat16 g_P3[kB*kNC*kHW];
__device__ __nv_bfloat16 g_P4[kB*kNC*kHW];
__device__ __nv_bfloat16 g_Vl[kB*kNC*kHW];
__device__ __nv_bfloat16 g_Kl[kB*kNC*kHW];
__device__ __nv_bfloat16 g_Qm[kB*kNC*kHW];
__device__ __nv_bfloat16 g_Kr[kB*kNC*kHW];
__device__ __nv_bfloat16 g_Vr[kB*kNC*kHW];
__device__ __nv_bfloat16 g_Abf[2ll*kB*kNC*kH*kH];
__device__ __nv_bfloat16 g_Ol[kB*kNC*kHW];
__device__ __nv_bfloat16 g_Or[kB*kNC*kHW];

// ---------------- helpers ----------------
__device__ __forceinline__ void ldsm4(uint32_t* r, uint32_t addr) {
  asm volatile("ldmatrix.sync.aligned.m8n8.x4.shared.b16 {%0,%1,%2,%3}, [%4];"
    : "=r"(r[0]), "=r"(r[1]), "=r"(r[2]), "=r"(r[3]) : "r"(addr));
}
__device__ __forceinline__ void ldsm4t(uint32_t* r, uint32_t addr) {
  asm volatile("ldmatrix.sync.aligned.m8n8.x4.trans.shared.b16 {%0,%1,%2,%3}, [%4];"
    : "=r"(r[0]), "=r"(r[1]), "=r"(r[2]), "=r"(r[3]) : "r"(addr));
}
__device__ __forceinline__ void mma16816(float* c, const uint32_t* a, uint32_t b0, uint32_t b1) {
  asm volatile("mma.sync.aligned.m16n8k16.row.col.f32.bf16.bf16.f32 "
    "{%0,%1,%2,%3}, {%4,%5,%6,%7}, {%8,%9}, {%0,%1,%2,%3};"
    : "+f"(c[0]), "+f"(c[1]), "+f"(c[2]), "+f"(c[3])
    : "r"(a[0]), "r"(a[1]), "r"(a[2]), "r"(a[3]), "r"(b0), "r"(b1));
}
__device__ __forceinline__ __nv_bfloat162 pack_bf2(float a, float b) {
  return __floats2bfloat162_rn(a, b);
}

struct ConvArgs {
  const __nv_bfloat16* inA;
  const __nv_bfloat16* inB;
  const float* w;
  const float* bias;
  const float* res;
  float* outF;
  __nv_bfloat16* outB;
};
struct DwArgs {
  const __nv_bfloat16* in;
  const float* w;
  const float* bias;
  __nv_bfloat16* out;
};

// ---------------- LayerNorm2d (both sides in one launch), bf16 out ----------------
__global__ __launch_bounds__(256) void ln_kernel(
    const float* __restrict__ x0, const float* __restrict__ x1,
    const float* __restrict__ g0, const float* __restrict__ be0,
    const float* __restrict__ g1, const float* __restrict__ be1,
    __nv_bfloat16* __restrict__ o0, __nv_bfloat16* __restrict__ o1) {
  int side = blockIdx.y;
  const float* x   = side ? x1 : x0;
  const float* gam = side ? g1 : g0;
  const float* bet = side ? be1 : be0;
  __nv_bfloat16* out = side ? o1 : o0;
  int idx = blockIdx.x * 256 + threadIdx.x;     // over B*HW
  int b = idx / kHW, p = idx % kHW;
  const float* xp = x + (size_t)b*kC*kHW + p;
  float v[kC];
  float s = 0.f;
#pragma unroll
  for (int c = 0; c < kC; c++) { v[c] = xp[(size_t)c*kHW]; s += v[c]; }
  float mu = s * (1.f/kC);
  float q = 0.f;
#pragma unroll
  for (int c = 0; c < kC; c++) { float d = v[c]-mu; q += d*d; }
  float rstd = rsqrtf(q*(1.f/kC) + 1e-6f);
  __nv_bfloat16* op = out + (size_t)b*kC*kHW + p;
#pragma unroll
  for (int c = 0; c < kC; c++)
    op[(size_t)c*kHW] = __float2bfloat16((v[c]-mu)*rstd*__ldg(&gam[c]) + __ldg(&bet[c]));
}

// ---------------- conv1x1 as bf16 HMMA GEMM, dual-branch launches ----------------
// blockIdx.y selects ConvArgs set. out[COUT, 128px] per block, 8 warps.
template<int COUT, int KDIM, bool DUAL, bool RES>
__global__ __launch_bounds__(256) void conv1x1_mma_kernel(ConvArgs c0, ConvArgs c1) {
  constexpr int WM = COUT/64;              // 2 (COUT=128) or 1 (COUT=64)
  constexpr int WN = 8/WM;                 // 4 or 8
  constexpr int WNC = 128/WN;              // 32 or 16
  constexpr int NF = WNC/8;                // 4 or 2
  constexpr int NB = (NF/2 > 0) ? NF/2 : 1;
  constexpr int KP = KDIM + 8;
  __shared__ __nv_bfloat16 sW[COUT*KP];
  __shared__ __nv_bfloat16 sX[KDIM*136];

  ConvArgs A = (blockIdx.y == 0) ? c0 : c1;
  int b  = blockIdx.z;
  int p0 = blockIdx.x * 128;
  int t  = threadIdx.x, warp = t >> 5, lane = t & 31;
  int wm = warp / WN, wn = warp % WN;

  // weights fp32 -> bf16 smem, vectorized (KDIM multiple of 4; float4 never crosses rows)
  for (int i = 4*t; i < COUT*KDIM; i += 1024) {
    int o = i / KDIM, k = i - o*KDIM;
    float4 wv = *(const float4*)(A.w + i);
    *(__nv_bfloat162*)&sW[o*KP + k]     = pack_bf2(wv.x, wv.y);
    *(__nv_bfloat162*)&sW[o*KP + k + 2] = pack_bf2(wv.z, wv.w);
  }
  // activations: sX[k][pix]
  for (int chunk = t; chunk < KDIM*16; chunk += 256) {
    int row = chunk >> 4, cg = chunk & 15;
    const __nv_bfloat16* src;
    if (DUAL) src = (row < kC) ? (A.inA + ((size_t)b*kC + row)*kHW)
                               : (A.inB + ((size_t)b*kC + (row-kC))*kHW);
    else      src = A.inA + ((size_t)b*KDIM + row)*kHW;
    *(uint4*)(sX + row*136 + cg*8) = *(const uint4*)(src + p0 + cg*8);
  }
  __syncthreads();

  float acc[4][NF][4];
#pragma unroll
  for (int i = 0; i < 4; i++)
#pragma unroll
    for (int j = 0; j < NF; j++)
#pragma unroll
      for (int k = 0; k < 4; k++) acc[i][j][k] = 0.f;

  uint32_t sWb = (uint32_t)__cvta_generic_to_shared(sW);
  uint32_t sXb = (uint32_t)__cvta_generic_to_shared(sX);

#pragma unroll
  for (int k0 = 0; k0 < KDIM; k0 += 16) {
    uint32_t a[4][4];
#pragma unroll
    for (int mf = 0; mf < 4; mf++) {
      int row = wm*64 + mf*16 + (lane & 15);
      int col = k0 + (lane >> 4)*8;
      ldsm4(a[mf], sWb + (uint32_t)(row*KP + col)*2);
    }
    uint32_t bfr[NB][4];
#pragma unroll
    for (int nb = 0; nb < NB; nb++) {
      int krow = k0 + ((lane >> 3) & 1)*8 + (lane & 7);
      int ncol = wn*WNC + nb*16 + (lane >> 4)*8;
      ldsm4t(bfr[nb], sXb + (uint32_t)(krow*136 + ncol)*2);
    }
#pragma unroll
    for (int mf = 0; mf < 4; mf++)
#pragma unroll
      for (int nf = 0; nf < NF; nf++)
        mma16816(acc[mf][nf], a[mf], bfr[nf>>1][(nf&1)*2], bfr[nf>>1][(nf&1)*2+1]);
  }

#pragma unroll
  for (int mf = 0; mf < 4; mf++) {
    int row = wm*64 + mf*16 + (lane >> 2);
    float bv0 = __ldg(&A.bias[row]);
    float bv1 = __ldg(&A.bias[row+8]);
#pragma unroll
    for (int nf = 0; nf < NF; nf++) {
      int col = wn*WNC + nf*8 + (lane & 3)*2;
      size_t o0 = ((size_t)b*COUT + row)*kHW + p0 + col;
      size_t o1 = o0 + (size_t)8*kHW;
      if (RES) {
        float2 r0 = *(const float2*)(A.res + o0);
        float2 r1 = *(const float2*)(A.res + o1);
        *(float2*)(A.outF + o0) = make_float2(acc[mf][nf][0]+bv0+r0.x, acc[mf][nf][1]+bv0+r0.y);
        *(float2*)(A.outF + o1) = make_float2(acc[mf][nf][2]+bv1+r1.x, acc[mf][nf][3]+bv1+r1.y);
      } else {
        *(__nv_bfloat162*)(A.outB + o0) = pack_bf2(acc[mf][nf][0]+bv0, acc[mf][nf][1]+bv0);
        *(__nv_bfloat162*)(A.outB + o1) = pack_bf2(acc[mf][nf][2]+bv1, acc[mf][nf][3]+bv1);
      }
    }
  }
}

// ---------------- depthwise 3x3, tiled smem, all 5 branches in one launch ----------------
// block: 8 rows x 384 cols of one (b,c); halo tile 10x384 in smem; 2 px per thread iter.
__global__ __launch_bounds__(256) void dwconv_kernel(
    DwArgs d0, DwArgs d1, DwArgs d2, DwArgs d3, DwArgs d4) {
  DwArgs a = d0;
  int z = blockIdx.z;
  if (z == 1) a = d1; else if (z == 2) a = d2; else if (z == 3) a = d3; else if (z == 4) a = d4;

  int bc = blockIdx.y;
  int c  = bc & (kNC-1);
  int h0 = blockIdx.x * 8;
  const __nv_bfloat16* ip = a.in + (size_t)bc*kHW;
  __nv_bfloat16* op = a.out + (size_t)bc*kHW;
  __shared__ __nv_bfloat16 tile[10][400];   // data at cols [8,392); halo col 7 and 392 zero
  int t = threadIdx.x;

  // zero halo columns (cols 0..7 and 392..399)
  for (int i = t; i < 160; i += 256) {
    int r = i >> 4, j = i & 15;
    tile[r][(j < 8) ? j : 384 + j] = __float2bfloat16(0.f);
  }
  // main fill: 10 rows x 48 uint4 chunks
  for (int i = t; i < 480; i += 256) {
    int r = i / 48, cg = i - r*48;
    int h = h0 - 1 + r;
    uint4 v = make_uint4(0u, 0u, 0u, 0u);
    if (h >= 0 && h < kH) v = *(const uint4*)(ip + (size_t)h*kW + cg*8);
    *(uint4*)&tile[r][8 + cg*8] = v;
  }
  __syncthreads();

  float wr[9];
#pragma unroll
  for (int j = 0; j < 9; j++) wr[j] = __ldg(&a.w[c*9 + j]);
  float bv = __ldg(&a.bias[c]);

#pragma unroll
  for (int i = 0; i < 6; i++) {
    int p = 2*(t + 256*i);              // 3072 px per block
    int row = p / 384, x = p - row*384;
    float a0 = bv, a1 = bv;
#pragma unroll
    for (int dy = 0; dy < 3; dy++)
#pragma unroll
      for (int dx = 0; dx < 3; dx++) {
        float wv = wr[dy*3 + dx];
        a0 += wv * __bfloat162float(tile[row+dy][7 + x + dx]);
        a1 += wv * __bfloat162float(tile[row+dy][8 + x + dx]);
      }
    *(__nv_bfloat162*)(op + (size_t)(h0+row)*kW + x) = pack_bf2(a0, a1);
  }
}

// ---------------- fused S = softmax(Q K^T * scale): bf16 A out ----------------
// Block: M=64 rows x full N=192, K=384. 128 threads = 4 warps; warp = 16 rows x 192 cols.
__global__ __launch_bounds__(128) void sgemm_softmax_kernel() {
  __shared__ __nv_bfloat16 sQ[64*40];
  __shared__ __nv_bfloat16 sK[192*40];
  int bc = blockIdx.y, side = blockIdx.z;
  const __nv_bfloat16* qb = g_Qm + (size_t)bc*kHW;
  const __nv_bfloat16* km = (side == 0 ? g_Kr : g_Kl) + (size_t)bc*kHW;
  int m0 = blockIdx.x * 64;
  int t = threadIdx.x, warp = t >> 5, lane = t & 31;

  float acc[24][4];
#pragma unroll
  for (int i = 0; i < 24; i++)
#pragma unroll
    for (int j = 0; j < 4; j++) acc[i][j] = 0.f;

  uint32_t sQb = (uint32_t)__cvta_generic_to_shared(sQ);
  uint32_t sKb = (uint32_t)__cvta_generic_to_shared(sK);

  for (int kb = 0; kb < kW; kb += 32) {
#pragma unroll
    for (int chunk = t; chunk < 256; chunk += 128) {        // Q: 64 x 32
      int row = chunk >> 2, cg = chunk & 3;
      *(uint4*)(sQ + row*40 + cg*8) = *(const uint4*)(qb + (size_t)(m0+row)*kW + kb + cg*8);
    }
#pragma unroll
    for (int chunk = t; chunk < 768; chunk += 128) {        // K: 192 x 32
      int row = chunk >> 2, cg = chunk & 3;
      *(uint4*)(sK + row*40 + cg*8) = *(const uint4*)(km + (size_t)row*kW + kb + cg*8);
    }
    __syncthreads();
#pragma unroll
    for (int ks = 0; ks < 2; ks++) {
      int k0 = ks*16;
      uint32_t a[4];
      {
        int row = warp*16 + (lane & 15);
        int col = k0 + (lane >> 4)*8;
        ldsm4(a, sQb + (uint32_t)(row*40 + col)*2);
      }
      uint32_t bf[12][4];
#pragma unroll
      for (int nb = 0; nb < 12; nb++) {
        int nrow = nb*16 + (lane >> 4)*8 + (lane & 7);
        int col  = k0 + ((lane >> 3) & 1)*8;
        ldsm4(bf[nb], sKb + (uint32_t)(nrow*40 + col)*2);
      }
#pragma unroll
      for (int nf = 0; nf < 24; nf++)
        mma16816(acc[nf], a, bf[nf>>1][(nf&1)*2], bf[nf>>1][(nf&1)*2+1]);
    }
    __syncthreads();
  }

#pragma unroll
  for (int nf = 0; nf < 24; nf++)
#pragma unroll
    for (int j = 0; j < 4; j++) acc[nf][j] *= kScale;

  float mx0 = -1e30f, mx1 = -1e30f;
#pragma unroll
  for (int nf = 0; nf < 24; nf++) {
    mx0 = fmaxf(mx0, fmaxf(acc[nf][0], acc[nf][1]));
    mx1 = fmaxf(mx1, fmaxf(acc[nf][2], acc[nf][3]));
  }
#pragma unroll
  for (int o = 1; o <= 2; o <<= 1) {
    mx0 = fmaxf(mx0, __shfl_xor_sync(0xffffffffu, mx0, o));
    mx1 = fmaxf(mx1, __shfl_xor_sync(0xffffffffu, mx1, o));
  }
  float s0 = 0.f, s1 = 0.f;
#pragma unroll
  for (int nf = 0; nf < 24; nf++) {
    acc[nf][0] = __expf(acc[nf][0]-mx0); s0 += acc[nf][0];
    acc[nf][1] = __expf(acc[nf][1]-mx0); s0 += acc[nf][1];
    acc[nf][2] = __expf(acc[nf][2]-mx1); s1 += acc[nf][2];
    acc[nf][3] = __expf(acc[nf][3]-mx1); s1 += acc[nf][3];
  }
#pragma unroll
  for (int o = 1; o <= 2; o <<= 1) {
    s0 += __shfl_xor_sync(0xffffffffu, s0, o);
    s1 += __shfl_xor_sync(0xffffffffu, s1, o);
  }
  float i0 = 1.f/s0, i1 = 1.f/s1;

  __nv_bfloat16* ap = g_Abf + ((size_t)side*(kB*kNC) + bc)*((size_t)kH*kH);
  int r0 = m0 + warp*16 + (lane >> 2);
#pragma unroll
  for (int nf = 0; nf < 24; nf++) {
    int c = nf*8 + (lane & 3)*2;
    *(__nv_bfloat162*)(ap + (size_t)r0*kH + c)     = pack_bf2(acc[nf][0]*i0, acc[nf][1]*i0);
    *(__nv_bfloat162*)(ap + (size_t)(r0+8)*kH + c) = pack_bf2(acc[nf][2]*i1, acc[nf][3]*i1);
  }
}

// ---------------- O = A @ V (bf16 HMMA, NN, bf16 out) ----------------
// Block tile 64 x 384 (full N), K=192. 256 threads = 8 warps (2x4), warp 32x96.
// A tile resident in smem (loaded once); V staged in 32-row k-chunks.
__global__ __launch_bounds__(256) void ogemm_bf16_kernel() {
  __shared__ __nv_bfloat16 sA[64*200];
  __shared__ __nv_bfloat16 sV[32*392];
  int bc = blockIdx.y, side = blockIdx.z;
  const __nv_bfloat16* ab = g_Abf + ((size_t)side*(kB*kNC) + bc)*((size_t)kH*kH);
  const __nv_bfloat16* vb = (side == 0 ? g_Vl : g_Vr) + (size_t)bc*kHW;
  __nv_bfloat16* ob = (side == 0 ? g_Ol : g_Or) + (size_t)bc*kHW;
  int m0 = blockIdx.x * 64;
  int t = threadIdx.x, warp = t >> 5, lane = t & 31;
  int wm = warp >> 2, wn = warp & 3;

  float acc[2][12][4];
#pragma unroll
  for (int i = 0; i < 2; i++)
#pragma unroll
    for (int j = 0; j < 12; j++)
#pragma unroll
      for (int k = 0; k < 4; k++) acc[i][j][k] = 0.f;

  uint32_t sAb = (uint32_t)__cvta_generic_to_shared(sA);
  uint32_t sVb = (uint32_t)__cvta_generic_to_shared(sV);

  // load full A tile: 64 rows x 192 cols = 1536 uint4 chunks
  for (int i = t; i < 1536; i += 256) {
    int row = i / 24, cg = i - row*24;
    *(uint4*)(sA + row*200 + cg*8) = *(const uint4*)(ab + (size_t)(m0+row)*kH + cg*8);
  }

  for (int kb = 0; kb < kH; kb += 32) {
    __syncthreads();                        // previous compute done before sV overwrite
    // load V chunk: 32 rows x 384 cols = 1536 uint4 chunks
    for (int i = t; i < 1536; i += 256) {
      int row = i / 48, cg = i - row*48;
      *(uint4*)(sV + row*392 + cg*8) = *(const uint4*)(vb + (size_t)(kb+row)*kW + cg*8);
    }
    __syncthreads();                        // sV (and first-iter sA) visible
#pragma unroll
    for (int ks = 0; ks < 2; ks++) {
      int k0 = ks*16;
      uint32_t a[2][4];
#pragma unroll
      for (int mf = 0; mf < 2; mf++) {
        int row = wm*32 + mf*16 + (lane & 15);
        int col = kb + k0 + (lane >> 4)*8;
        ldsm4(a[mf], sAb + (uint32_t)(row*200 + col)*2);
      }
      uint32_t b[6][4];
#pragma unroll
      for (int nb = 0; nb < 6; nb++) {
        int krow = k0 + ((lane >> 3) & 1)*8 + (lane & 7);
        int ncol = wn*96 + nb*16 + (lane >> 4)*8;
        ldsm4t(b[nb], sVb + (uint32_t)(krow*392 + ncol)*2);
      }
#pragma unroll
      for (int mf = 0; mf < 2; mf++)
#pragma unroll
        for (int nf = 0; nf < 12; nf++)
          mma16816(acc[mf][nf], a[mf], b[nf>>1][(nf&1)*2], b[nf>>1][(nf&1)*2+1]);
    }
  }

#pragma unroll
  for (int mf = 0; mf < 2; mf++)
#pragma unroll
    for (int nf = 0; nf < 12; nf++) {
      int r = m0 + wm*32 + mf*16 + (lane >> 2);
      int c = wn*96 + nf*8 + (lane & 3)*2;
      *(__nv_bfloat162*)(ob + (size_t)r*kW + c)     = pack_bf2(acc[mf][nf][0], acc[mf][nf][1]);
      *(__nv_bfloat162*)(ob + (size_t)(r+8)*kW + c) = pack_bf2(acc[mf][nf][2], acc[mf][nf][3]);
    }
}

// ---------------- launch ----------------
extern "C" void kernel_launch(void* const* d_in, const int* in_sizes, int n_in,
                              void* d_out, int out_size) {
  const float* x_l   = (const float*)d_in[0];
  const float* x_r   = (const float*)d_in[1];
  const float* ln1_g = (const float*)d_in[2];
  const float* ln1_b = (const float*)d_in[3];
  const float* ln2_g = (const float*)d_in[4];
  const float* ln2_b = (const float*)d_in[5];
  const float* w1 = (const float*)d_in[6];   const float* b1 = (const float*)d_in[7];
  const float* w2 = (const float*)d_in[8];   const float* b2 = (const float*)d_in[9];
  const float* w3 = (const float*)d_in[10];  const float* b3 = (const float*)d_in[11];
  const float* w4 = (const float*)d_in[12];  const float* b4 = (const float*)d_in[13];
  const float* w5 = (const float*)d_in[14];  const float* b5 = (const float*)d_in[15];
  const float* dw1 = (const float*)d_in[16]; const float* db1 = (const float*)d_in[17];
  const float* dw2 = (const float*)d_in[18]; const float* db2 = (const float*)d_in[19];
  const float* dw3 = (const float*)d_in[20]; const float* db3 = (const float*)d_in[21];
  const float* dw4 = (const float*)d_in[22]; const float* db4 = (const float*)d_in[23];
  const float* dw5 = (const float*)d_in[24]; const float* db5 = (const float*)d_in[25];
  const float* w6 = (const float*)d_in[26];  const float* b6 = (const float*)d_in[27];
  const float* w7 = (const float*)d_in[28];  const float* b7 = (const float*)d_in[29];
  float* out = (float*)d_out;

  __nv_bfloat16 *nl, *nr, *P0, *P1, *P2, *P3, *P4, *Vl, *Kl, *Qm, *Kr, *Vr, *Ol, *Or;
  cudaGetSymbolAddress((void**)&nl, g_nl);
  cudaGetSymbolAddress((void**)&nr, g_nr);
  cudaGetSymbolAddress((void**)&P0, g_P0);
  cudaGetSymbolAddress((void**)&P1, g_P1);
  cudaGetSymbolAddress((void**)&P2, g_P2);
  cudaGetSymbolAddress((void**)&P3, g_P3);
  cudaGetSymbolAddress((void**)&P4, g_P4);
  cudaGetSymbolAddress((void**)&Vl, g_Vl);
  cudaGetSymbolAddress((void**)&Kl, g_Kl);
  cudaGetSymbolAddress((void**)&Qm, g_Qm);
  cudaGetSymbolAddress((void**)&Kr, g_Kr);
  cudaGetSymbolAddress((void**)&Vr, g_Vr);
  cudaGetSymbolAddress((void**)&Ol, g_Ol);
  cudaGetSymbolAddress((void**)&Or, g_Or);

  // 1. LayerNorm2d (both sides, one launch)
  ln_kernel<<<dim3(kB*kHW/256, 2), 256>>>(x_l, x_r, ln1_g, ln1_b, ln2_g, ln2_b, nl, nr);

  // 2. conv1x1 branches: (w1,w2 | nl), (w3 | nl+nr), (w4,w5 | nr)
  ConvArgs a1 = { nl, nullptr, w1, b1, nullptr, nullptr, P0 };
  ConvArgs a2 = { nl, nullptr, w2, b2, nullptr, nullptr, P1 };
  ConvArgs a3 = { nl, nr,      w3, b3, nullptr, nullptr, P2 };
  ConvArgs a4 = { nr, nullptr, w4, b4, nullptr, nullptr, P3 };
  ConvArgs a5 = { nr, nullptr, w5, b5, nullptr, nullptr, P4 };
  conv1x1_mma_kernel<kNC, kC, false, false><<<dim3(kHW/128, 2, kB), 256>>>(a1, a2);
  conv1x1_mma_kernel<kNC, 2*kC, true, false><<<dim3(kHW/128, 1, kB), 256>>>(a3, a3);
  conv1x1_mma_kernel<kNC, kC, false, false><<<dim3(kHW/128, 2, kB), 256>>>(a4, a5);

  // 3. all five depthwise 3x3 convs in one launch
  DwArgs dA = { P0, dw1, db1, Vl };
  DwArgs dB = { P1, dw2, db2, Kl };
  DwArgs dC = { P2, dw3, db3, Qm };
  DwArgs dD = { P3, dw4, db4, Kr };
  DwArgs dE = { P4, dw5, db5, Vr };
  dwconv_kernel<<<dim3(kH/8, kB*kNC, 5), 256>>>(dA, dB, dC, dD, dE);

  // 4. fused S-GEMM + softmax -> bf16 A; O = A @ V -> bf16 O
  sgemm_softmax_kernel<<<dim3(3, kB*kNC, 2), 128>>>();
  ogemm_bf16_kernel<<<dim3(3, kB*kNC, 2), 256>>>();

  // 5. final conv1x1 + residual (both sides, one launch), fp32 out
  ConvArgs f0 = { Ol, nullptr, w6, b6, x_l, out, nullptr };
  ConvArgs f1 = { Or, nullptr, w7, b7, x_r, out + (size_t)kB*kC*kHW, nullptr };
  conv1x1_mma_kernel<kC, kNC, false, true><<<dim3(kHW/128, 2, kB), 256>>>(f0, f1);
}

// round 11
// speedup vs baseline: 3.7784x; 1.0902x over previous
#include <cuda_runtime.h>
#include <cuda_bf16.h>
#include <math.h>
#include <stdint.h>

constexpr int kB  = 8;
constexpr int kC  = 64;
constexpr int kNC = 128;
constexpr int kH  = 192;
constexpr int kW  = 384;
constexpr int kHW = kH * kW;                    // 73728
constexpr float kScale = 0.08838834764831845f;  // 1/sqrt(128)

// ---------------- scratch (device globals; no runtime allocation) ----------------
__device__ __nv_bfloat16 g_nl[kB*kC*kHW];
__device__ __nv_bfloat16 g_nr[kB*kC*kHW];
__device__ __nv_bfloat16 g_P0[kB*kNC*kHW];
__device__ __nv_bfloat16 g_P1[kB*kNC*kHW];
__device__ __nv_bfloat16 g_P2[kB*kNC*kHW];
__device__ __nv_bfloat16 g_P3[kB*kNC*kHW];
__device__ __nv_bfloat16 g_P4[kB*kNC*kHW];
__device__ __nv_bfloat16 g_Vl[kB*kNC*kHW];
__device__ __nv_bfloat16 g_Kl[kB*kNC*kHW];
__device__ __nv_bfloat16 g_Qm[kB*kNC*kHW];
__device__ __nv_bfloat16 g_Kr[kB*kNC*kHW];
__device__ __nv_bfloat16 g_Vr[kB*kNC*kHW];
__device__ __nv_bfloat16 g_Ol[kB*kNC*kHW];
__device__ __nv_bfloat16 g_Or[kB*kNC*kHW];
__device__ __nv_bfloat16 g_Wbf[65536];   // bf16 copies of w1..w7

// ---------------- helpers ----------------
__device__ __forceinline__ void ldsm4(uint32_t* r, uint32_t addr) {
  asm volatile("ldmatrix.sync.aligned.m8n8.x4.shared.b16 {%0,%1,%2,%3}, [%4];"
    : "=r"(r[0]), "=r"(r[1]), "=r"(r[2]), "=r"(r[3]) : "r"(addr));
}
__device__ __forceinline__ void ldsm4t(uint32_t* r, uint32_t addr) {
  asm volatile("ldmatrix.sync.aligned.m8n8.x4.trans.shared.b16 {%0,%1,%2,%3}, [%4];"
    : "=r"(r[0]), "=r"(r[1]), "=r"(r[2]), "=r"(r[3]) : "r"(addr));
}
__device__ __forceinline__ void mma16816(float* c, const uint32_t* a, uint32_t b0, uint32_t b1) {
  asm volatile("mma.sync.aligned.m16n8k16.row.col.f32.bf16.bf16.f32 "
    "{%0,%1,%2,%3}, {%4,%5,%6,%7}, {%8,%9}, {%0,%1,%2,%3};"
    : "+f"(c[0]), "+f"(c[1]), "+f"(c[2]), "+f"(c[3])
    : "r"(a[0]), "r"(a[1]), "r"(a[2]), "r"(a[3]), "r"(b0), "r"(b1));
}
__device__ __forceinline__ __nv_bfloat162 pack_bf2(float a, float b) {
  return __floats2bfloat162_rn(a, b);
}

struct ConvArgs {
  const __nv_bfloat16* inA;
  const __nv_bfloat16* inB;
  const __nv_bfloat16* w;      // bf16, pre-converted
  const float* bias;
  const float* res;
  float* outF;
  __nv_bfloat16* outB;
};
struct DwArgs {
  const __nv_bfloat16* in;
  const float* w;
  const float* bias;
  __nv_bfloat16* out;
};

// ---------------- weight pre-conversion (fp32 -> bf16), one shot ----------------
__global__ __launch_bounds__(256) void wconv_kernel(
    const float* __restrict__ w1, const float* __restrict__ w2,
    const float* __restrict__ w3, const float* __restrict__ w4,
    const float* __restrict__ w5, const float* __restrict__ w6,
    const float* __restrict__ w7) {
  int i = blockIdx.x*256 + threadIdx.x;              // 65536 total
  const float* src; int off;
  if      (i < 8192)  { src = w1; off = 0;     }
  else if (i < 16384) { src = w2; off = 8192;  }
  else if (i < 32768) { src = w3; off = 16384; }
  else if (i < 40960) { src = w4; off = 32768; }
  else if (i < 49152) { src = w5; off = 40960; }
  else if (i < 57344) { src = w6; off = 49152; }
  else                { src = w7; off = 57344; }
  g_Wbf[i] = __float2bfloat16(src[i - off]);
}

// ---------------- LayerNorm2d (both sides in one launch), bf16 out ----------------
__global__ __launch_bounds__(256) void ln_kernel(
    const float* __restrict__ x0, const float* __restrict__ x1,
    const float* __restrict__ g0, const float* __restrict__ be0,
    const float* __restrict__ g1, const float* __restrict__ be1,
    __nv_bfloat16* __restrict__ o0, __nv_bfloat16* __restrict__ o1) {
  int side = blockIdx.y;
  const float* x   = side ? x1 : x0;
  const float* gam = side ? g1 : g0;
  const float* bet = side ? be1 : be0;
  __nv_bfloat16* out = side ? o1 : o0;
  int idx = blockIdx.x * 256 + threadIdx.x;     // over B*HW
  int b = idx / kHW, p = idx % kHW;
  const float* xp = x + (size_t)b*kC*kHW + p;
  float v[kC];
  float s = 0.f;
#pragma unroll
  for (int c = 0; c < kC; c++) { v[c] = xp[(size_t)c*kHW]; s += v[c]; }
  float mu = s * (1.f/kC);
  float q = 0.f;
#pragma unroll
  for (int c = 0; c < kC; c++) { float d = v[c]-mu; q += d*d; }
  float rstd = rsqrtf(q*(1.f/kC) + 1e-6f);
  __nv_bfloat16* op = out + (size_t)b*kC*kHW + p;
#pragma unroll
  for (int c = 0; c < kC; c++)
    op[(size_t)c*kHW] = __float2bfloat16((v[c]-mu)*rstd*__ldg(&gam[c]) + __ldg(&bet[c]));
}

// ---------------- conv1x1 as bf16 HMMA GEMM, dual-branch launches ----------------
template<int COUT, int KDIM, bool DUAL, bool RES>
__global__ __launch_bounds__(256) void conv1x1_mma_kernel(ConvArgs c0, ConvArgs c1) {
  constexpr int WM = COUT/64;              // 2 (COUT=128) or 1 (COUT=64)
  constexpr int WN = 8/WM;                 // 4 or 8
  constexpr int WNC = 128/WN;              // 32 or 16
  constexpr int NF = WNC/8;                // 4 or 2
  constexpr int NB = (NF/2 > 0) ? NF/2 : 1;
  constexpr int KP = KDIM + 8;
  __shared__ __nv_bfloat16 sW[COUT*KP];
  __shared__ __nv_bfloat16 sX[KDIM*136];

  ConvArgs A = (blockIdx.y == 0) ? c0 : c1;
  int b  = blockIdx.z;
  int p0 = blockIdx.x * 128;
  int t  = threadIdx.x, warp = t >> 5, lane = t & 31;
  int wm = warp / WN, wn = warp % WN;

  // bf16 weights, vectorized copy (rows multiple of 8; uint4 never crosses rows)
  for (int i = 8*t; i < COUT*KDIM; i += 2048) {
    int o = i / KDIM, k = i - o*KDIM;
    *(uint4*)&sW[o*KP + k] = *(const uint4*)(A.w + i);
  }
  // activations: sX[k][pix]
  for (int chunk = t; chunk < KDIM*16; chunk += 256) {
    int row = chunk >> 4, cg = chunk & 15;
    const __nv_bfloat16* src;
    if (DUAL) src = (row < kC) ? (A.inA + ((size_t)b*kC + row)*kHW)
                               : (A.inB + ((size_t)b*kC + (row-kC))*kHW);
    else      src = A.inA + ((size_t)b*KDIM + row)*kHW;
    *(uint4*)(sX + row*136 + cg*8) = *(const uint4*)(src + p0 + cg*8);
  }
  __syncthreads();

  float acc[4][NF][4];
#pragma unroll
  for (int i = 0; i < 4; i++)
#pragma unroll
    for (int j = 0; j < NF; j++)
#pragma unroll
      for (int k = 0; k < 4; k++) acc[i][j][k] = 0.f;

  uint32_t sWb = (uint32_t)__cvta_generic_to_shared(sW);
  uint32_t sXb = (uint32_t)__cvta_generic_to_shared(sX);

#pragma unroll
  for (int k0 = 0; k0 < KDIM; k0 += 16) {
    uint32_t a[4][4];
#pragma unroll
    for (int mf = 0; mf < 4; mf++) {
      int row = wm*64 + mf*16 + (lane & 15);
      int col = k0 + (lane >> 4)*8;
      ldsm4(a[mf], sWb + (uint32_t)(row*KP + col)*2);
    }
    uint32_t bfr[NB][4];
#pragma unroll
    for (int nb = 0; nb < NB; nb++) {
      int krow = k0 + ((lane >> 3) & 1)*8 + (lane & 7);
      int ncol = wn*WNC + nb*16 + (lane >> 4)*8;
      ldsm4t(bfr[nb], sXb + (uint32_t)(krow*136 + ncol)*2);
    }
#pragma unroll
    for (int mf = 0; mf < 4; mf++)
#pragma unroll
      for (int nf = 0; nf < NF; nf++)
        mma16816(acc[mf][nf], a[mf], bfr[nf>>1][(nf&1)*2], bfr[nf>>1][(nf&1)*2+1]);
  }

#pragma unroll
  for (int mf = 0; mf < 4; mf++) {
    int row = wm*64 + mf*16 + (lane >> 2);
    float bv0 = __ldg(&A.bias[row]);
    float bv1 = __ldg(&A.bias[row+8]);
#pragma unroll
    for (int nf = 0; nf < NF; nf++) {
      int col = wn*WNC + nf*8 + (lane & 3)*2;
      size_t o0 = ((size_t)b*COUT + row)*kHW + p0 + col;
      size_t o1 = o0 + (size_t)8*kHW;
      if (RES) {
        float2 r0 = *(const float2*)(A.res + o0);
        float2 r1 = *(const float2*)(A.res + o1);
        *(float2*)(A.outF + o0) = make_float2(acc[mf][nf][0]+bv0+r0.x, acc[mf][nf][1]+bv0+r0.y);
        *(float2*)(A.outF + o1) = make_float2(acc[mf][nf][2]+bv1+r1.x, acc[mf][nf][3]+bv1+r1.y);
      } else {
        *(__nv_bfloat162*)(A.outB + o0) = pack_bf2(acc[mf][nf][0]+bv0, acc[mf][nf][1]+bv0);
        *(__nv_bfloat162*)(A.outB + o1) = pack_bf2(acc[mf][nf][2]+bv1, acc[mf][nf][3]+bv1);
      }
    }
  }
}

// ---------------- depthwise 3x3, tiled smem, all 5 branches in one launch ----------------
__global__ __launch_bounds__(256) void dwconv_kernel(
    DwArgs d0, DwArgs d1, DwArgs d2, DwArgs d3, DwArgs d4) {
  DwArgs a = d0;
  int z = blockIdx.z;
  if (z == 1) a = d1; else if (z == 2) a = d2; else if (z == 3) a = d3; else if (z == 4) a = d4;

  int bc = blockIdx.y;
  int c  = bc & (kNC-1);
  int h0 = blockIdx.x * 8;
  const __nv_bfloat16* ip = a.in + (size_t)bc*kHW;
  __nv_bfloat16* op = a.out + (size_t)bc*kHW;
  __shared__ __nv_bfloat16 tile[10][400];
  int t = threadIdx.x;

  for (int i = t; i < 160; i += 256) {
    int r = i >> 4, j = i & 15;
    tile[r][(j < 8) ? j : 384 + j] = __float2bfloat16(0.f);
  }
  for (int i = t; i < 480; i += 256) {
    int r = i / 48, cg = i - r*48;
    int h = h0 - 1 + r;
    uint4 v = make_uint4(0u, 0u, 0u, 0u);
    if (h >= 0 && h < kH) v = *(const uint4*)(ip + (size_t)h*kW + cg*8);
    *(uint4*)&tile[r][8 + cg*8] = v;
  }
  __syncthreads();

  float wr[9];
#pragma unroll
  for (int j = 0; j < 9; j++) wr[j] = __ldg(&a.w[c*9 + j]);
  float bv = __ldg(&a.bias[c]);

#pragma unroll
  for (int i = 0; i < 6; i++) {
    int p = 2*(t + 256*i);
    int row = p / 384, x = p - row*384;
    float a0 = bv, a1 = bv;
#pragma unroll
    for (int dy = 0; dy < 3; dy++)
#pragma unroll
      for (int dx = 0; dx < 3; dx++) {
        float wv = wr[dy*3 + dx];
        a0 += wv * __bfloat162float(tile[row+dy][7 + x + dx]);
        a1 += wv * __bfloat162float(tile[row+dy][8 + x + dx]);
      }
    *(__nv_bfloat162*)(op + (size_t)(h0+row)*kW + x) = pack_bf2(a0, a1);
  }
}

// ---------------- fused attention: O = softmax(Q K^T * scale) @ V ----------------
// Block = 64 Q-rows. Phase 1: S(64x192) in regs -> softmax -> bf16 A in smem.
// Phase 2: O(64x384) in three 128-wide n-chunks, V streamed in 32-k chunks.
__global__ __launch_bounds__(128) void attn_kernel() {
  __shared__ __nv_bfloat16 sA[64*200];               // softmaxed A, stride 200
  __shared__ __nv_bfloat16 sQK[64*40 + 192*40];      // phase1: Q|K ; phase2: V chunk
  int bc = blockIdx.y, side = blockIdx.z;
  const __nv_bfloat16* qb = g_Qm + (size_t)bc*kHW;
  const __nv_bfloat16* km = (side == 0 ? g_Kr : g_Kl) + (size_t)bc*kHW;
  const __nv_bfloat16* vb = (side == 0 ? g_Vl : g_Vr) + (size_t)bc*kHW;
  __nv_bfloat16* ob = (side == 0 ? g_Ol : g_Or) + (size_t)bc*kHW;
  int m0 = blockIdx.x * 64;
  int t = threadIdx.x, warp = t >> 5, lane = t & 31;

  __nv_bfloat16* sQ = sQK;
  __nv_bfloat16* sK = sQK + 64*40;
  uint32_t sQb = (uint32_t)__cvta_generic_to_shared(sQ);
  uint32_t sKb = (uint32_t)__cvta_generic_to_shared(sK);
  uint32_t sAb = (uint32_t)__cvta_generic_to_shared(sA);
  uint32_t sVb = sQb;

  // ---- phase 1: S = Q K^T, warp = 16 rows x 192 cols ----
  {
    float acc[24][4];
#pragma unroll
    for (int i = 0; i < 24; i++)
#pragma unroll
      for (int j = 0; j < 4; j++) acc[i][j] = 0.f;

    for (int kb = 0; kb < kW; kb += 32) {
#pragma unroll
      for (int chunk = t; chunk < 256; chunk += 128) {      // Q: 64 x 32
        int row = chunk >> 2, cg = chunk & 3;
        *(uint4*)(sQ + row*40 + cg*8) = *(const uint4*)(qb + (size_t)(m0+row)*kW + kb + cg*8);
      }
#pragma unroll
      for (int chunk = t; chunk < 768; chunk += 128) {      // K: 192 x 32
        int row = chunk >> 2, cg = chunk & 3;
        *(uint4*)(sK + row*40 + cg*8) = *(const uint4*)(km + (size_t)row*kW + kb + cg*8);
      }
      __syncthreads();
#pragma unroll
      for (int ks = 0; ks < 2; ks++) {
        int k0 = ks*16;
        uint32_t a[4];
        {
          int row = warp*16 + (lane & 15);
          int col = k0 + (lane >> 4)*8;
          ldsm4(a, sQb + (uint32_t)(row*40 + col)*2);
        }
        uint32_t bf[12][4];
#pragma unroll
        for (int nb = 0; nb < 12; nb++) {
          int nrow = nb*16 + (lane >> 4)*8 + (lane & 7);
          int col  = k0 + ((lane >> 3) & 1)*8;
          ldsm4(bf[nb], sKb + (uint32_t)(nrow*40 + col)*2);
        }
#pragma unroll
        for (int nf = 0; nf < 24; nf++)
          mma16816(acc[nf], a, bf[nf>>1][(nf&1)*2], bf[nf>>1][(nf&1)*2+1]);
      }
      __syncthreads();
    }

#pragma unroll
    for (int nf = 0; nf < 24; nf++)
#pragma unroll
      for (int j = 0; j < 4; j++) acc[nf][j] *= kScale;

    float mx0 = -1e30f, mx1 = -1e30f;
#pragma unroll
    for (int nf = 0; nf < 24; nf++) {
      mx0 = fmaxf(mx0, fmaxf(acc[nf][0], acc[nf][1]));
      mx1 = fmaxf(mx1, fmaxf(acc[nf][2], acc[nf][3]));
    }
#pragma unroll
    for (int o = 1; o <= 2; o <<= 1) {
      mx0 = fmaxf(mx0, __shfl_xor_sync(0xffffffffu, mx0, o));
      mx1 = fmaxf(mx1, __shfl_xor_sync(0xffffffffu, mx1, o));
    }
    float s0 = 0.f, s1 = 0.f;
#pragma unroll
    for (int nf = 0; nf < 24; nf++) {
      acc[nf][0] = __expf(acc[nf][0]-mx0); s0 += acc[nf][0];
      acc[nf][1] = __expf(acc[nf][1]-mx0); s0 += acc[nf][1];
      acc[nf][2] = __expf(acc[nf][2]-mx1); s1 += acc[nf][2];
      acc[nf][3] = __expf(acc[nf][3]-mx1); s1 += acc[nf][3];
    }
#pragma unroll
    for (int o = 1; o <= 2; o <<= 1) {
      s0 += __shfl_xor_sync(0xffffffffu, s0, o);
      s1 += __shfl_xor_sync(0xffffffffu, s1, o);
    }
    float i0 = 1.f/s0, i1 = 1.f/s1;

    int r0 = warp*16 + (lane >> 2);
#pragma unroll
    for (int nf = 0; nf < 24; nf++) {
      int c = nf*8 + (lane & 3)*2;
      *(__nv_bfloat162*)&sA[r0*200 + c]     = pack_bf2(acc[nf][0]*i0, acc[nf][1]*i0);
      *(__nv_bfloat162*)&sA[(r0+8)*200 + c] = pack_bf2(acc[nf][2]*i1, acc[nf][3]*i1);
    }
  }
  __syncthreads();

  // ---- phase 2: O = A @ V, warp grid 2x2, n-chunks of 128 ----
  int wm = warp >> 1, wn = warp & 1;
#pragma unroll
  for (int n0 = 0; n0 < kW; n0 += 128) {
    float oac[2][8][4];
#pragma unroll
    for (int i = 0; i < 2; i++)
#pragma unroll
      for (int j = 0; j < 8; j++)
#pragma unroll
        for (int k = 0; k < 4; k++) oac[i][j][k] = 0.f;

    for (int kb = 0; kb < kH; kb += 32) {
      __syncthreads();
      // V chunk: 32 rows x 128 cols, stride 136
      for (int i = t; i < 512; i += 128) {
        int row = i >> 4, cg = i & 15;
        *(uint4*)(sQK + row*136 + cg*8) = *(const uint4*)(vb + (size_t)(kb+row)*kW + n0 + cg*8);
      }
      __syncthreads();
#pragma unroll
      for (int ks = 0; ks < 2; ks++) {
        int k0 = ks*16;
        uint32_t a[2][4];
#pragma unroll
        for (int mf = 0; mf < 2; mf++) {
          int row = wm*32 + mf*16 + (lane & 15);
          int col = kb + k0 + (lane >> 4)*8;
          ldsm4(a[mf], sAb + (uint32_t)(row*200 + col)*2);
        }
        uint32_t b[4][4];
#pragma unroll
        for (int nb = 0; nb < 4; nb++) {
          int krow = k0 + ((lane >> 3) & 1)*8 + (lane & 7);
          int ncol = wn*64 + nb*16 + (lane >> 4)*8;
          ldsm4t(b[nb], sVb + (uint32_t)(krow*136 + ncol)*2);
        }
#pragma unroll
        for (int mf = 0; mf < 2; mf++)
#pragma unroll
          for (int nf = 0; nf < 8; nf++)
            mma16816(oac[mf][nf], a[mf], b[nf>>1][(nf&1)*2], b[nf>>1][(nf&1)*2+1]);
      }
    }
#pragma unroll
    for (int mf = 0; mf < 2; mf++)
#pragma unroll
      for (int nf = 0; nf < 8; nf++) {
        int r = m0 + wm*32 + mf*16 + (lane >> 2);
        int c = n0 + wn*64 + nf*8 + (lane & 3)*2;
        *(__nv_bfloat162*)(ob + (size_t)r*kW + c)     = pack_bf2(oac[mf][nf][0], oac[mf][nf][1]);
        *(__nv_bfloat162*)(ob + (size_t)(r+8)*kW + c) = pack_bf2(oac[mf][nf][2], oac[mf][nf][3]);
      }
  }
}

// ---------------- launch ----------------
extern "C" void kernel_launch(void* const* d_in, const int* in_sizes, int n_in,
                              void* d_out, int out_size) {
  const float* x_l   = (const float*)d_in[0];
  const float* x_r   = (const float*)d_in[1];
  const float* ln1_g = (const float*)d_in[2];
  const float* ln1_b = (const float*)d_in[3];
  const float* ln2_g = (const float*)d_in[4];
  const float* ln2_b = (const float*)d_in[5];
  const float* w1 = (const float*)d_in[6];   const float* b1 = (const float*)d_in[7];
  const float* w2 = (const float*)d_in[8];   const float* b2 = (const float*)d_in[9];
  const float* w3 = (const float*)d_in[10];  const float* b3 = (const float*)d_in[11];
  const float* w4 = (const float*)d_in[12];  const float* b4 = (const float*)d_in[13];
  const float* w5 = (const float*)d_in[14];  const float* b5 = (const float*)d_in[15];
  const float* dw1 = (const float*)d_in[16]; const float* db1 = (const float*)d_in[17];
  const float* dw2 = (const float*)d_in[18]; const float* db2 = (const float*)d_in[19];
  const float* dw3 = (const float*)d_in[20]; const float* db3 = (const float*)d_in[21];
  const float* dw4 = (const float*)d_in[22]; const float* db4 = (const float*)d_in[23];
  const float* dw5 = (const float*)d_in[24]; const float* db5 = (const float*)d_in[25];
  const float* w6 = (const float*)d_in[26];  const float* b6 = (const float*)d_in[27];
  const float* w7 = (const float*)d_in[28];  const float* b7 = (const float*)d_in[29];
  float* out = (float*)d_out;

  __nv_bfloat16 *nl, *nr, *P0, *P1, *P2, *P3, *P4, *Vl, *Kl, *Qm, *Kr, *Vr, *Ol, *Or, *Wbf;
  cudaGetSymbolAddress((void**)&nl, g_nl);
  cudaGetSymbolAddress((void**)&nr, g_nr);
  cudaGetSymbolAddress((void**)&P0, g_P0);
  cudaGetSymbolAddress((void**)&P1, g_P1);
  cudaGetSymbolAddress((void**)&P2, g_P2);
  cudaGetSymbolAddress((void**)&P3, g_P3);
  cudaGetSymbolAddress((void**)&P4, g_P4);
  cudaGetSymbolAddress((void**)&Vl, g_Vl);
  cudaGetSymbolAddress((void**)&Kl, g_Kl);
  cudaGetSymbolAddress((void**)&Qm, g_Qm);
  cudaGetSymbolAddress((void**)&Kr, g_Kr);
  cudaGetSymbolAddress((void**)&Vr, g_Vr);
  cudaGetSymbolAddress((void**)&Ol, g_Ol);
  cudaGetSymbolAddress((void**)&Or, g_Or);
  cudaGetSymbolAddress((void**)&Wbf, g_Wbf);

  // 0. weights -> bf16 arena
  wconv_kernel<<<256, 256>>>(w1, w2, w3, w4, w5, w6, w7);

  // 1. LayerNorm2d (both sides)
  ln_kernel<<<dim3(kB*kHW/256, 2), 256>>>(x_l, x_r, ln1_g, ln1_b, ln2_g, ln2_b, nl, nr);

  // 2. conv1x1 branches with bf16 weights
  ConvArgs a1 = { nl, nullptr, Wbf,         b1, nullptr, nullptr, P0 };
  ConvArgs a2 = { nl, nullptr, Wbf + 8192,  b2, nullptr, nullptr, P1 };
  ConvArgs a3 = { nl, nr,      Wbf + 16384, b3, nullptr, nullptr, P2 };
  ConvArgs a4 = { nr, nullptr, Wbf + 32768, b4, nullptr, nullptr, P3 };
  ConvArgs a5 = { nr, nullptr, Wbf + 40960, b5, nullptr, nullptr, P4 };
  conv1x1_mma_kernel<kNC, kC, false, false><<<dim3(kHW/128, 2, kB), 256>>>(a1, a2);
  conv1x1_mma_kernel<kNC, 2*kC, true, false><<<dim3(kHW/128, 1, kB), 256>>>(a3, a3);
  conv1x1_mma_kernel<kNC, kC, false, false><<<dim3(kHW/128, 2, kB), 256>>>(a4, a5);

  // 3. all five depthwise 3x3 convs in one launch
  DwArgs dA = { P0, dw1, db1, Vl };
  DwArgs dB = { P1, dw2, db2, Kl };
  DwArgs dC = { P2, dw3, db3, Qm };
  DwArgs dD = { P3, dw4, db4, Kr };
  DwArgs dE = { P4, dw5, db5, Vr };
  dwconv_kernel<<<dim3(kH/8, kB*kNC, 5), 256>>>(dA, dB, dC, dD, dE);

  // 4. fused attention (S + softmax + O)
  attn_kernel<<<dim3(3, kB*kNC, 2), 128>>>();

  // 5. final conv1x1 + residual (both sides), fp32 out
  ConvArgs f0 = { Ol, nullptr, Wbf + 49152, b6, x_l, out, nullptr };
  ConvArgs f1 = { Or, nullptr, Wbf + 57344, b7, x_r, out + (size_t)kB*kC*kHW, nullptr };
  conv1x1_mma_kernel<kC, kNC, false, true><<<dim3(kHW/128, 2, kB), 256>>>(f0, f1);
}

// round 12
// speedup vs baseline: 4.6091x; 1.2199x over previous
#include <cuda_runtime.h>
#include <cuda_bf16.h>
#include <math.h>
#include <stdint.h>

constexpr int kB  = 8;
constexpr int kC  = 64;
constexpr int kNC = 128;
constexpr int kH  = 192;
constexpr int kW  = 384;
constexpr int kHW = kH * kW;                    // 73728
constexpr float kScale = 0.08838834764831845f;  // 1/sqrt(128)

// ---------------- scratch (device globals; no runtime allocation) ----------------
__device__ __nv_bfloat16 g_nl[kB*kC*kHW];
__device__ __nv_bfloat16 g_nr[kB*kC*kHW];
__device__ __nv_bfloat16 g_P0[kB*kNC*kHW];
__device__ __nv_bfloat16 g_P1[kB*kNC*kHW];
__device__ __nv_bfloat16 g_P2[kB*kNC*kHW];
__device__ __nv_bfloat16 g_P3[kB*kNC*kHW];
__device__ __nv_bfloat16 g_P4[kB*kNC*kHW];
__device__ __nv_bfloat16 g_Vl[kB*kNC*kHW];
__device__ __nv_bfloat16 g_Kl[kB*kNC*kHW];
__device__ __nv_bfloat16 g_Qm[kB*kNC*kHW];
__device__ __nv_bfloat16 g_Kr[kB*kNC*kHW];
__device__ __nv_bfloat16 g_Vr[kB*kNC*kHW];
__device__ __nv_bfloat16 g_Ol[kB*kNC*kHW];
__device__ __nv_bfloat16 g_Or[kB*kNC*kHW];
__device__ __nv_bfloat16 g_Wbf[65536];   // bf16 copies of w1..w7

// ---------------- helpers ----------------
__device__ __forceinline__ void ldsm4(uint32_t* r, uint32_t addr) {
  asm volatile("ldmatrix.sync.aligned.m8n8.x4.shared.b16 {%0,%1,%2,%3}, [%4];"
    : "=r"(r[0]), "=r"(r[1]), "=r"(r[2]), "=r"(r[3]) : "r"(addr));
}
__device__ __forceinline__ void ldsm4t(uint32_t* r, uint32_t addr) {
  asm volatile("ldmatrix.sync.aligned.m8n8.x4.trans.shared.b16 {%0,%1,%2,%3}, [%4];"
    : "=r"(r[0]), "=r"(r[1]), "=r"(r[2]), "=r"(r[3]) : "r"(addr));
}
__device__ __forceinline__ void mma16816(float* c, const uint32_t* a, uint32_t b0, uint32_t b1) {
  asm volatile("mma.sync.aligned.m16n8k16.row.col.f32.bf16.bf16.f32 "
    "{%0,%1,%2,%3}, {%4,%5,%6,%7}, {%8,%9}, {%0,%1,%2,%3};"
    : "+f"(c[0]), "+f"(c[1]), "+f"(c[2]), "+f"(c[3])
    : "r"(a[0]), "r"(a[1]), "r"(a[2]), "r"(a[3]), "r"(b0), "r"(b1));
}
__device__ __forceinline__ __nv_bfloat162 pack_bf2(float a, float b) {
  return __floats2bfloat162_rn(a, b);
}
__device__ __forceinline__ void cp16(uint32_t dst, const void* src) {
  asm volatile("cp.async.cg.shared.global [%0], [%1], 16;" :: "r"(dst), "l"(src));
}
__device__ __forceinline__ void cp_commit() { asm volatile("cp.async.commit_group;"); }
template<int N> __device__ __forceinline__ void cp_wait() {
  asm volatile("cp.async.wait_group %0;" :: "n"(N));
}

struct ConvArgs {
  const __nv_bfloat16* inA;
  const __nv_bfloat16* inB;
  const __nv_bfloat16* w;      // bf16, pre-converted
  const float* bias;
  const float* res;
  float* outF;
  __nv_bfloat16* outB;
};
struct DwArgs {
  const __nv_bfloat16* in;
  const float* w;
  const float* bias;
  __nv_bfloat16* out;
};

// ---------------- weight pre-conversion (fp32 -> bf16), one shot ----------------
__global__ __launch_bounds__(256) void wconv_kernel(
    const float* __restrict__ w1, const float* __restrict__ w2,
    const float* __restrict__ w3, const float* __restrict__ w4,
    const float* __restrict__ w5, const float* __restrict__ w6,
    const float* __restrict__ w7) {
  int i = blockIdx.x*256 + threadIdx.x;              // 65536 total
  const float* src; int off;
  if      (i < 8192)  { src = w1; off = 0;     }
  else if (i < 16384) { src = w2; off = 8192;  }
  else if (i < 32768) { src = w3; off = 16384; }
  else if (i < 40960) { src = w4; off = 32768; }
  else if (i < 49152) { src = w5; off = 40960; }
  else if (i < 57344) { src = w6; off = 49152; }
  else                { src = w7; off = 57344; }
  g_Wbf[i] = __float2bfloat16(src[i - off]);
}

// ---------------- LayerNorm2d (both sides in one launch), bf16 out ----------------
__global__ __launch_bounds__(256) void ln_kernel(
    const float* __restrict__ x0, const float* __restrict__ x1,
    const float* __restrict__ g0, const float* __restrict__ be0,
    const float* __restrict__ g1, const float* __restrict__ be1,
    __nv_bfloat16* __restrict__ o0, __nv_bfloat16* __restrict__ o1) {
  int side = blockIdx.y;
  const float* x   = side ? x1 : x0;
  const float* gam = side ? g1 : g0;
  const float* bet = side ? be1 : be0;
  __nv_bfloat16* out = side ? o1 : o0;
  int idx = blockIdx.x * 256 + threadIdx.x;     // over B*HW
  int b = idx / kHW, p = idx % kHW;
  const float* xp = x + (size_t)b*kC*kHW + p;
  float v[kC];
  float s = 0.f;
#pragma unroll
  for (int c = 0; c < kC; c++) { v[c] = xp[(size_t)c*kHW]; s += v[c]; }
  float mu = s * (1.f/kC);
  float q = 0.f;
#pragma unroll
  for (int c = 0; c < kC; c++) { float d = v[c]-mu; q += d*d; }
  float rstd = rsqrtf(q*(1.f/kC) + 1e-6f);
  __nv_bfloat16* op = out + (size_t)b*kC*kHW + p;
#pragma unroll
  for (int c = 0; c < kC; c++)
    op[(size_t)c*kHW] = __float2bfloat16((v[c]-mu)*rstd*__ldg(&gam[c]) + __ldg(&bet[c]));
}

// ---------------- conv1x1 as bf16 HMMA GEMM, 256-px tiles, cp.async pipelined ----------------
// blockIdx.y selects among 4 ConvArgs. Two 128-px chunks per block, double-buffered.
template<int COUT, int KDIM, bool DUAL, bool RES>
__global__ __launch_bounds__(256) void conv1x1_mma_kernel(
    ConvArgs c0, ConvArgs c1, ConvArgs c2, ConvArgs c3) {
  constexpr int WM = COUT/64;              // 2 (COUT=128) or 1 (COUT=64)
  constexpr int WN = 8/WM;                 // 4 or 8
  constexpr int WNC = 128/WN;              // 32 or 16
  constexpr int NF = WNC/8;                // 4 or 2
  constexpr int NB = (NF >= 2) ? NF/2 : 1;
  constexpr int KP = KDIM + 8;
  __shared__ __nv_bfloat16 sW[COUT*KP];
  __shared__ __nv_bfloat16 sX[2*KDIM*136];

  ConvArgs A = c0;
  {
    int y = blockIdx.y;
    if (y == 1) A = c1; else if (y == 2) A = c2; else if (y == 3) A = c3;
  }
  int b  = blockIdx.z;
  int p0 = blockIdx.x * 256;
  int t  = threadIdx.x, warp = t >> 5, lane = t & 31;
  int wm = warp / WN, wn = warp % WN;

  uint32_t sWb = (uint32_t)__cvta_generic_to_shared(sW);
  uint32_t sXb = (uint32_t)__cvta_generic_to_shared(sX);

  // async fill X chunk 0 (px [p0, p0+128))
  for (int chunk = t; chunk < KDIM*16; chunk += 256) {
    int row = chunk >> 4, cg = chunk & 15;
    const __nv_bfloat16* src;
    if (DUAL) src = (row < kC) ? (A.inA + ((size_t)b*kC + row)*kHW)
                               : (A.inB + ((size_t)b*kC + (row-kC))*kHW);
    else      src = A.inA + ((size_t)b*KDIM + row)*kHW;
    cp16(sXb + (uint32_t)(row*136 + cg*8)*2, src + p0 + cg*8);
  }
  cp_commit();
  // weights (overlap with the async fill)
  for (int i = 8*t; i < COUT*KDIM; i += 2048) {
    int o = i / KDIM, k = i - o*KDIM;
    *(uint4*)&sW[o*KP + k] = *(const uint4*)(A.w + i);
  }
  cp_wait<0>(); __syncthreads();

  // async fill X chunk 1 (px [p0+128, p0+256))
  for (int chunk = t; chunk < KDIM*16; chunk += 256) {
    int row = chunk >> 4, cg = chunk & 15;
    const __nv_bfloat16* src;
    if (DUAL) src = (row < kC) ? (A.inA + ((size_t)b*kC + row)*kHW)
                               : (A.inB + ((size_t)b*kC + (row-kC))*kHW);
    else      src = A.inA + ((size_t)b*KDIM + row)*kHW;
    cp16(sXb + (uint32_t)(KDIM*136 + row*136 + cg*8)*2, src + p0 + 128 + cg*8);
  }
  cp_commit();

#pragma unroll
  for (int pc = 0; pc < 2; pc++) {
    float acc[4][NF][4];
#pragma unroll
    for (int i = 0; i < 4; i++)
#pragma unroll
      for (int j = 0; j < NF; j++)
#pragma unroll
        for (int k = 0; k < 4; k++) acc[i][j][k] = 0.f;

    uint32_t xbase = sXb + (uint32_t)(pc*KDIM*136)*2;
#pragma unroll
    for (int k0 = 0; k0 < KDIM; k0 += 16) {
      uint32_t a[4][4];
#pragma unroll
      for (int mf = 0; mf < 4; mf++) {
        int row = wm*64 + mf*16 + (lane & 15);
        int col = k0 + (lane >> 4)*8;
        ldsm4(a[mf], sWb + (uint32_t)(row*KP + col)*2);
      }
      uint32_t bfr[NB][4];
#pragma unroll
      for (int nb = 0; nb < NB; nb++) {
        int krow = k0 + ((lane >> 3) & 1)*8 + (lane & 7);
        int ncol = wn*WNC + nb*16 + (lane >> 4)*8;
        ldsm4t(bfr[nb], xbase + (uint32_t)(krow*136 + ncol)*2);
      }
#pragma unroll
      for (int mf = 0; mf < 4; mf++)
#pragma unroll
        for (int nf = 0; nf < NF; nf++)
          mma16816(acc[mf][nf], a[mf], bfr[nf>>1][(nf&1)*2], bfr[nf>>1][(nf&1)*2+1]);
    }

    int px = p0 + pc*128;
#pragma unroll
    for (int mf = 0; mf < 4; mf++) {
      int row = wm*64 + mf*16 + (lane >> 2);
      float bv0 = __ldg(&A.bias[row]);
      float bv1 = __ldg(&A.bias[row+8]);
#pragma unroll
      for (int nf = 0; nf < NF; nf++) {
        int col = wn*WNC + nf*8 + (lane & 3)*2;
        size_t o0 = ((size_t)b*COUT + row)*kHW + px + col;
        size_t o1 = o0 + (size_t)8*kHW;
        if (RES) {
          float2 r0 = *(const float2*)(A.res + o0);
          float2 r1 = *(const float2*)(A.res + o1);
          *(float2*)(A.outF + o0) = make_float2(acc[mf][nf][0]+bv0+r0.x, acc[mf][nf][1]+bv0+r0.y);
          *(float2*)(A.outF + o1) = make_float2(acc[mf][nf][2]+bv1+r1.x, acc[mf][nf][3]+bv1+r1.y);
        } else {
          *(__nv_bfloat162*)(A.outB + o0) = pack_bf2(acc[mf][nf][0]+bv0, acc[mf][nf][1]+bv0);
          *(__nv_bfloat162*)(A.outB + o1) = pack_bf2(acc[mf][nf][2]+bv1, acc[mf][nf][3]+bv1);
        }
      }
    }
    if (pc == 0) { cp_wait<0>(); __syncthreads(); }
  }
}

// ---------------- depthwise 3x3, tiled smem, all 5 branches in one launch ----------------
__global__ __launch_bounds__(256) void dwconv_kernel(
    DwArgs d0, DwArgs d1, DwArgs d2, DwArgs d3, DwArgs d4) {
  DwArgs a = d0;
  int z = blockIdx.z;
  if (z == 1) a = d1; else if (z == 2) a = d2; else if (z == 3) a = d3; else if (z == 4) a = d4;

  int bc = blockIdx.y;
  int c  = bc & (kNC-1);
  int h0 = blockIdx.x * 8;
  const __nv_bfloat16* ip = a.in + (size_t)bc*kHW;
  __nv_bfloat16* op = a.out + (size_t)bc*kHW;
  __shared__ __nv_bfloat16 tile[10][400];
  int t = threadIdx.x;

  for (int i = t; i < 160; i += 256) {
    int r = i >> 4, j = i & 15;
    tile[r][(j < 8) ? j : 384 + j] = __float2bfloat16(0.f);
  }
  for (int i = t; i < 480; i += 256) {
    int r = i / 48, cg = i - r*48;
    int h = h0 - 1 + r;
    uint4 v = make_uint4(0u, 0u, 0u, 0u);
    if (h >= 0 && h < kH) v = *(const uint4*)(ip + (size_t)h*kW + cg*8);
    *(uint4*)&tile[r][8 + cg*8] = v;
  }
  __syncthreads();

  float wr[9];
#pragma unroll
  for (int j = 0; j < 9; j++) wr[j] = __ldg(&a.w[c*9 + j]);
  float bv = __ldg(&a.bias[c]);

#pragma unroll
  for (int i = 0; i < 6; i++) {
    int p = 2*(t + 256*i);
    int row = p / 384, x = p - row*384;
    float a0 = bv, a1 = bv;
#pragma unroll
    for (int dy = 0; dy < 3; dy++)
#pragma unroll
      for (int dx = 0; dx < 3; dx++) {
        float wv = wr[dy*3 + dx];
        a0 += wv * __bfloat162float(tile[row+dy][7 + x + dx]);
        a1 += wv * __bfloat162float(tile[row+dy][8 + x + dx]);
      }
    *(__nv_bfloat162*)(op + (size_t)(h0+row)*kW + x) = pack_bf2(a0, a1);
  }
}

// ---------------- fused attention: O = softmax(Q K^T * scale) @ V ----------------
// Block = 64 Q-rows. Phase 1: S(64x192) in regs -> softmax -> bf16 A in smem.
// Phase 2: O(64x384) in three 128-wide n-chunks; V double-buffered via cp.async.
__global__ __launch_bounds__(128) void attn_kernel() {
  __shared__ __nv_bfloat16 sA[64*200];               // softmaxed A, stride 200
  __shared__ __nv_bfloat16 sQK[64*40 + 192*40];      // phase1: Q|K ; phase2: 2x V chunk (32x136 each)
  int bc = blockIdx.y, side = blockIdx.z;
  const __nv_bfloat16* qb = g_Qm + (size_t)bc*kHW;
  const __nv_bfloat16* km = (side == 0 ? g_Kr : g_Kl) + (size_t)bc*kHW;
  const __nv_bfloat16* vb = (side == 0 ? g_Vl : g_Vr) + (size_t)bc*kHW;
  __nv_bfloat16* ob = (side == 0 ? g_Ol : g_Or) + (size_t)bc*kHW;
  int m0 = blockIdx.x * 64;
  int t = threadIdx.x, warp = t >> 5, lane = t & 31;

  __nv_bfloat16* sQ = sQK;
  __nv_bfloat16* sK = sQK + 64*40;
  uint32_t sQb = (uint32_t)__cvta_generic_to_shared(sQ);
  uint32_t sKb = (uint32_t)__cvta_generic_to_shared(sK);
  uint32_t sAb = (uint32_t)__cvta_generic_to_shared(sA);
  uint32_t sVb = sQb;                                 // phase2 V buffers overlay sQK

  // ---- phase 1: S = Q K^T, warp = 16 rows x 192 cols ----
  {
    float acc[24][4];
#pragma unroll
    for (int i = 0; i < 24; i++)
#pragma unroll
      for (int j = 0; j < 4; j++) acc[i][j] = 0.f;

    for (int kb = 0; kb < kW; kb += 32) {
#pragma unroll
      for (int chunk = t; chunk < 256; chunk += 128) {      // Q: 64 x 32
        int row = chunk >> 2, cg = chunk & 3;
        *(uint4*)(sQ + row*40 + cg*8) = *(const uint4*)(qb + (size_t)(m0+row)*kW + kb + cg*8);
      }
#pragma unroll
      for (int chunk = t; chunk < 768; chunk += 128) {      // K: 192 x 32
        int row = chunk >> 2, cg = chunk & 3;
        *(uint4*)(sK + row*40 + cg*8) = *(const uint4*)(km + (size_t)row*kW + kb + cg*8);
      }
      __syncthreads();
#pragma unroll
      for (int ks = 0; ks < 2; ks++) {
        int k0 = ks*16;
        uint32_t a[4];
        {
          int row = warp*16 + (lane & 15);
          int col = k0 + (lane >> 4)*8;
          ldsm4(a, sQb + (uint32_t)(row*40 + col)*2);
        }
        uint32_t bf[12][4];
#pragma unroll
        for (int nb = 0; nb < 12; nb++) {
          int nrow = nb*16 + (lane >> 4)*8 + (lane & 7);
          int col  = k0 + ((lane >> 3) & 1)*8;
          ldsm4(bf[nb], sKb + (uint32_t)(nrow*40 + col)*2);
        }
#pragma unroll
        for (int nf = 0; nf < 24; nf++)
          mma16816(acc[nf], a, bf[nf>>1][(nf&1)*2], bf[nf>>1][(nf&1)*2+1]);
      }
      __syncthreads();
    }

#pragma unroll
    for (int nf = 0; nf < 24; nf++)
#pragma unroll
      for (int j = 0; j < 4; j++) acc[nf][j] *= kScale;

    float mx0 = -1e30f, mx1 = -1e30f;
#pragma unroll
    for (int nf = 0; nf < 24; nf++) {
      mx0 = fmaxf(mx0, fmaxf(acc[nf][0], acc[nf][1]));
      mx1 = fmaxf(mx1, fmaxf(acc[nf][2], acc[nf][3]));
    }
#pragma unroll
    for (int o = 1; o <= 2; o <<= 1) {
      mx0 = fmaxf(mx0, __shfl_xor_sync(0xffffffffu, mx0, o));
      mx1 = fmaxf(mx1, __shfl_xor_sync(0xffffffffu, mx1, o));
    }
    float s0 = 0.f, s1 = 0.f;
#pragma unroll
    for (int nf = 0; nf < 24; nf++) {
      acc[nf][0] = __expf(acc[nf][0]-mx0); s0 += acc[nf][0];
      acc[nf][1] = __expf(acc[nf][1]-mx0); s0 += acc[nf][1];
      acc[nf][2] = __expf(acc[nf][2]-mx1); s1 += acc[nf][2];
      acc[nf][3] = __expf(acc[nf][3]-mx1); s1 += acc[nf][3];
    }
#pragma unroll
    for (int o = 1; o <= 2; o <<= 1) {
      s0 += __shfl_xor_sync(0xffffffffu, s0, o);
      s1 += __shfl_xor_sync(0xffffffffu, s1, o);
    }
    float i0 = 1.f/s0, i1 = 1.f/s1;

    int r0 = warp*16 + (lane >> 2);
#pragma unroll
    for (int nf = 0; nf < 24; nf++) {
      int c = nf*8 + (lane & 3)*2;
      *(__nv_bfloat162*)&sA[r0*200 + c]     = pack_bf2(acc[nf][0]*i0, acc[nf][1]*i0);
      *(__nv_bfloat162*)&sA[(r0+8)*200 + c] = pack_bf2(acc[nf][2]*i1, acc[nf][3]*i1);
    }
  }
  __syncthreads();

  // ---- phase 2: O = A @ V, warp grid 2x2, n-chunks of 128, V double-buffered ----
  int wm = warp >> 1, wn = warp & 1;
#pragma unroll
  for (int n0 = 0; n0 < kW; n0 += 128) {
    float oac[2][8][4];
#pragma unroll
    for (int i = 0; i < 2; i++)
#pragma unroll
      for (int j = 0; j < 8; j++)
#pragma unroll
        for (int k = 0; k < 4; k++) oac[i][j][k] = 0.f;

    // preload k-chunk 0 -> buffer 0
    for (int i = t; i < 512; i += 128) {
      int row = i >> 4, cg = i & 15;
      cp16(sVb + (uint32_t)(row*136 + cg*8)*2, vb + (size_t)row*kW + n0 + cg*8);
    }
    cp_commit();

    for (int kc = 0; kc < 6; kc++) {           // k-chunks of 32
      if (kc < 5) {
        uint32_t dst = sVb + (uint32_t)(((kc+1)&1)*32*136)*2;
        const __nv_bfloat16* vsrc = vb + (size_t)(kc+1)*32*kW + n0;
        for (int i = t; i < 512; i += 128) {
          int row = i >> 4, cg = i & 15;
          cp16(dst + (uint32_t)(row*136 + cg*8)*2, vsrc + (size_t)row*kW + cg*8);
        }
        cp_commit();
        cp_wait<1>();
      } else {
        cp_wait<0>();
      }
      __syncthreads();                          // V buffer (kc&1) ready
      uint32_t vbase = sVb + (uint32_t)((kc&1)*32*136)*2;
#pragma unroll
      for (int ks = 0; ks < 2; ks++) {
        int k0 = ks*16;
        uint32_t a[2][4];
#pragma unroll
        for (int mf = 0; mf < 2; mf++) {
          int row = wm*32 + mf*16 + (lane & 15);
          int col = kc*32 + k0 + (lane >> 4)*8;
          ldsm4(a[mf], sAb + (uint32_t)(row*200 + col)*2);
        }
        uint32_t b[4][4];
#pragma unroll
        for (int nb = 0; nb < 4; nb++) {
          int krow = k0 + ((lane >> 3) & 1)*8 + (lane & 7);
          int ncol = wn*64 + nb*16 + (lane >> 4)*8;
          ldsm4t(b[nb], vbase + (uint32_t)(krow*136 + ncol)*2);
        }
#pragma unroll
        for (int mf = 0; mf < 2; mf++)
#pragma unroll
          for (int nf = 0; nf < 8; nf++)
            mma16816(oac[mf][nf], a[mf], b[nf>>1][(nf&1)*2], b[nf>>1][(nf&1)*2+1]);
      }
      __syncthreads();                          // all reads done before buffer reuse
    }
#pragma unroll
    for (int mf = 0; mf < 2; mf++)
#pragma unroll
      for (int nf = 0; nf < 8; nf++) {
        int r = m0 + wm*32 + mf*16 + (lane >> 2);
        int c = n0 + wn*64 + nf*8 + (lane & 3)*2;
        *(__nv_bfloat162*)(ob + (size_t)r*kW + c)     = pack_bf2(oac[mf][nf][0], oac[mf][nf][1]);
        *(__nv_bfloat162*)(ob + (size_t)(r+8)*kW + c) = pack_bf2(oac[mf][nf][2], oac[mf][nf][3]);
      }
  }
}

// ---------------- launch ----------------
extern "C" void kernel_launch(void* const* d_in, const int* in_sizes, int n_in,
                              void* d_out, int out_size) {
  const float* x_l   = (const float*)d_in[0];
  const float* x_r   = (const float*)d_in[1];
  const float* ln1_g = (const float*)d_in[2];
  const float* ln1_b = (const float*)d_in[3];
  const float* ln2_g = (const float*)d_in[4];
  const float* ln2_b = (const float*)d_in[5];
  const float* w1 = (const float*)d_in[6];   const float* b1 = (const float*)d_in[7];
  const float* w2 = (const float*)d_in[8];   const float* b2 = (const float*)d_in[9];
  const float* w3 = (const float*)d_in[10];  const float* b3 = (const float*)d_in[11];
  const float* w4 = (const float*)d_in[12];  const float* b4 = (const float*)d_in[13];
  const float* w5 = (const float*)d_in[14];  const float* b5 = (const float*)d_in[15];
  const float* dw1 = (const float*)d_in[16]; const float* db1 = (const float*)d_in[17];
  const float* dw2 = (const float*)d_in[18]; const float* db2 = (const float*)d_in[19];
  const float* dw3 = (const float*)d_in[20]; const float* db3 = (const float*)d_in[21];
  const float* dw4 = (const float*)d_in[22]; const float* db4 = (const float*)d_in[23];
  const float* dw5 = (const float*)d_in[24]; const float* db5 = (const float*)d_in[25];
  const float* w6 = (const float*)d_in[26];  const float* b6 = (const float*)d_in[27];
  const float* w7 = (const float*)d_in[28];  const float* b7 = (const float*)d_in[29];
  float* out = (float*)d_out;

  __nv_bfloat16 *nl, *nr, *P0, *P1, *P2, *P3, *P4, *Vl, *Kl, *Qm, *Kr, *Vr, *Ol, *Or, *Wbf;
  cudaGetSymbolAddress((void**)&nl, g_nl);
  cudaGetSymbolAddress((void**)&nr, g_nr);
  cudaGetSymbolAddress((void**)&P0, g_P0);
  cudaGetSymbolAddress((void**)&P1, g_P1);
  cudaGetSymbolAddress((void**)&P2, g_P2);
  cudaGetSymbolAddress((void**)&P3, g_P3);
  cudaGetSymbolAddress((void**)&P4, g_P4);
  cudaGetSymbolAddress((void**)&Vl, g_Vl);
  cudaGetSymbolAddress((void**)&Kl, g_Kl);
  cudaGetSymbolAddress((void**)&Qm, g_Qm);
  cudaGetSymbolAddress((void**)&Kr, g_Kr);
  cudaGetSymbolAddress((void**)&Vr, g_Vr);
  cudaGetSymbolAddress((void**)&Ol, g_Ol);
  cudaGetSymbolAddress((void**)&Or, g_Or);
  cudaGetSymbolAddress((void**)&Wbf, g_Wbf);

  // 0. weights -> bf16 arena
  wconv_kernel<<<256, 256>>>(w1, w2, w3, w4, w5, w6, w7);

  // 1. LayerNorm2d (both sides)
  ln_kernel<<<dim3(kB*kHW/256, 2), 256>>>(x_l, x_r, ln1_g, ln1_b, ln2_g, ln2_b, nl, nr);

  // 2. conv1x1 branches: four single-input branches in one launch, dual-input alone
  ConvArgs a1 = { nl, nullptr, Wbf,         b1, nullptr, nullptr, P0 };
  ConvArgs a2 = { nl, nullptr, Wbf + 8192,  b2, nullptr, nullptr, P1 };
  ConvArgs a3 = { nl, nr,      Wbf + 16384, b3, nullptr, nullptr, P2 };
  ConvArgs a4 = { nr, nullptr, Wbf + 32768, b4, nullptr, nullptr, P3 };
  ConvArgs a5 = { nr, nullptr, Wbf + 40960, b5, nullptr, nullptr, P4 };
  conv1x1_mma_kernel<kNC, kC, false, false><<<dim3(kHW/256, 4, kB), 256>>>(a1, a2, a4, a5);
  conv1x1_mma_kernel<kNC, 2*kC, true, false><<<dim3(kHW/256, 1, kB), 256>>>(a3, a3, a3, a3);

  // 3. all five depthwise 3x3 convs in one launch
  DwArgs dA = { P0, dw1, db1, Vl };
  DwArgs dB = { P1, dw2, db2, Kl };
  DwArgs dC = { P2, dw3, db3, Qm };
  DwArgs dD = { P3, dw4, db4, Kr };
  DwArgs dE = { P4, dw5, db5, Vr };
  dwconv_kernel<<<dim3(kH/8, kB*kNC, 5), 256>>>(dA, dB, dC, dD, dE);

  // 4. fused attention (S + softmax + O)
  attn_kernel<<<dim3(3, kB*kNC, 2), 128>>>();

  // 5. final conv1x1 + residual (both sides), fp32 out
  ConvArgs f0 = { Ol, nullptr, Wbf + 49152, b6, x_l, out, nullptr };
  ConvArgs f1 = { Or, nullptr, Wbf + 57344, b7, x_r, out + (size_t)kB*kC*kHW, nullptr };
  conv1x1_mma_kernel<kC, kNC, false, true><<<dim3(kHW/256, 2, kB), 256>>>(f0, f1, f0, f1);
}

// round 14
// speedup vs baseline: 4.9393x; 1.0716x over previous
#include <cuda_runtime.h>
#include <cuda_bf16.h>
#include <math.h>
#include <stdint.h>

constexpr int kB  = 8;
constexpr int kC  = 64;
constexpr int kNC = 128;
constexpr int kH  = 192;
constexpr int kW  = 384;
constexpr int kHW = kH * kW;                    // 73728
constexpr float kScale = 0.08838834764831845f;  // 1/sqrt(128)

// ---------------- scratch (device globals; no runtime allocation) ----------------
__device__ __nv_bfloat16 g_nl[kB*kC*kHW];
__device__ __nv_bfloat16 g_nr[kB*kC*kHW];
__device__ __nv_bfloat16 g_P0[kB*kNC*kHW];
__device__ __nv_bfloat16 g_P1[kB*kNC*kHW];
__device__ __nv_bfloat16 g_P2[kB*kNC*kHW];
__device__ __nv_bfloat16 g_P3[kB*kNC*kHW];
__device__ __nv_bfloat16 g_P4[kB*kNC*kHW];
__device__ __nv_bfloat16 g_Vl[kB*kNC*kHW];
__device__ __nv_bfloat16 g_Kl[kB*kNC*kHW];
__device__ __nv_bfloat16 g_Qm[kB*kNC*kHW];
__device__ __nv_bfloat16 g_Kr[kB*kNC*kHW];
__device__ __nv_bfloat16 g_Vr[kB*kNC*kHW];
__device__ __nv_bfloat16 g_Ol[kB*kNC*kHW];
__device__ __nv_bfloat16 g_Or[kB*kNC*kHW];
__device__ __nv_bfloat16 g_Wbf[65536];   // bf16 copies of w1..w7

// ---------------- helpers ----------------
__device__ __forceinline__ void ldsm4(uint32_t* r, uint32_t addr) {
  asm volatile("ldmatrix.sync.aligned.m8n8.x4.shared.b16 {%0,%1,%2,%3}, [%4];"
    : "=r"(r[0]), "=r"(r[1]), "=r"(r[2]), "=r"(r[3]) : "r"(addr));
}
__device__ __forceinline__ void ldsm4t(uint32_t* r, uint32_t addr) {
  asm volatile("ldmatrix.sync.aligned.m8n8.x4.trans.shared.b16 {%0,%1,%2,%3}, [%4];"
    : "=r"(r[0]), "=r"(r[1]), "=r"(r[2]), "=r"(r[3]) : "r"(addr));
}
__device__ __forceinline__ void mma16816(float* c, const uint32_t* a, uint32_t b0, uint32_t b1) {
  asm volatile("mma.sync.aligned.m16n8k16.row.col.f32.bf16.bf16.f32 "
    "{%0,%1,%2,%3}, {%4,%5,%6,%7}, {%8,%9}, {%0,%1,%2,%3};"
    : "+f"(c[0]), "+f"(c[1]), "+f"(c[2]), "+f"(c[3])
    : "r"(a[0]), "r"(a[1]), "r"(a[2]), "r"(a[3]), "r"(b0), "r"(b1));
}
__device__ __forceinline__ __nv_bfloat162 pack_bf2(float a, float b) {
  return __floats2bfloat162_rn(a, b);
}
__device__ __forceinline__ void cp16(uint32_t dst, const void* src) {
  asm volatile("cp.async.cg.shared.global [%0], [%1], 16;" :: "r"(dst), "l"(src));
}
__device__ __forceinline__ void cp_commit() { asm volatile("cp.async.commit_group;"); }
template<int N> __device__ __forceinline__ void cp_wait() {
  asm volatile("cp.async.wait_group %0;" :: "n"(N));
}

struct ConvArgs {
  const __nv_bfloat16* inA;
  const __nv_bfloat16* inB;
  const __nv_bfloat16* w;      // bf16, pre-converted
  const float* bias;
  const float* res;
  float* outF;
  __nv_bfloat16* outB;
};
struct DwArgs {
  const __nv_bfloat16* in;
  const float* w;
  const float* bias;
  __nv_bfloat16* out;
};

// ---------------- weight pre-conversion (fp32 -> bf16), one shot ----------------
__global__ __launch_bounds__(256) void wconv_kernel(
    const float* __restrict__ w1, const float* __restrict__ w2,
    const float* __restrict__ w3, const float* __restrict__ w4,
    const float* __restrict__ w5, const float* __restrict__ w6,
    const float* __restrict__ w7) {
  int i = blockIdx.x*256 + threadIdx.x;              // 65536 total
  const float* src; int off;
  if      (i < 8192)  { src = w1; off = 0;     }
  else if (i < 16384) { src = w2; off = 8192;  }
  else if (i < 32768) { src = w3; off = 16384; }
  else if (i < 40960) { src = w4; off = 32768; }
  else if (i < 49152) { src = w5; off = 40960; }
  else if (i < 57344) { src = w6; off = 49152; }
  else                { src = w7; off = 57344; }
  g_Wbf[i] = __float2bfloat16(src[i - off]);
}

// ---------------- LayerNorm2d (both sides in one launch), bf16 out ----------------
__global__ __launch_bounds__(256) void ln_kernel(
    const float* __restrict__ x0, const float* __restrict__ x1,
    const float* __restrict__ g0, const float* __restrict__ be0,
    const float* __restrict__ g1, const float* __restrict__ be1,
    __nv_bfloat16* __restrict__ o0, __nv_bfloat16* __restrict__ o1) {
  int side = blockIdx.y;
  const float* x   = side ? x1 : x0;
  const float* gam = side ? g1 : g0;
  const float* bet = side ? be1 : be0;
  __nv_bfloat16* out = side ? o1 : o0;
  int idx = blockIdx.x * 256 + threadIdx.x;     // over B*HW
  int b = idx / kHW, p = idx % kHW;
  const float* xp = x + (size_t)b*kC*kHW + p;
  float v[kC];
  float s = 0.f;
#pragma unroll
  for (int c = 0; c < kC; c++) { v[c] = xp[(size_t)c*kHW]; s += v[c]; }
  float mu = s * (1.f/kC);
  float q = 0.f;
#pragma unroll
  for (int c = 0; c < kC; c++) { float d = v[c]-mu; q += d*d; }
  float rstd = rsqrtf(q*(1.f/kC) + 1e-6f);
  __nv_bfloat16* op = out + (size_t)b*kC*kHW + p;
#pragma unroll
  for (int c = 0; c < kC; c++)
    op[(size_t)c*kHW] = __float2bfloat16((v[c]-mu)*rstd*__ldg(&gam[c]) + __ldg(&bet[c]));
}

// ---------------- conv1x1 v4: weight-persistent, 64-px tiles, K streamed ----------------
// Block = COUT x 256px as 4 sequential 64-px tiles; K in 32-row cp.async chunks (2 bufs).
// 8 warps as 2x4: warp tile = (COUT/2) rows x 16 px.
template<int COUT, int KDIM, bool DUAL, bool RES>
__global__ __launch_bounds__(256) void conv1x1_mma_kernel(
    ConvArgs c0, ConvArgs c1, ConvArgs c2, ConvArgs c3) {
  constexpr int KCH = KDIM/32;             // k chunks per tile
  constexpr int PT  = 4;                   // px tiles per block
  constexpr int NS  = PT*KCH;              // total pipeline stages
  constexpr int KP  = KDIM + 8;
  constexpr int MF  = COUT/32;             // m-frags per warp (4 or 2)
  __shared__ __nv_bfloat16 sW[COUT*KP];
  __shared__ __nv_bfloat16 sX[2*32*72];

  ConvArgs A = c0;
  { int y = blockIdx.y; if (y == 1) A = c1; else if (y == 2) A = c2; else if (y == 3) A = c3; }
  int b  = blockIdx.z;
  int p0 = blockIdx.x * 256;
  int t  = threadIdx.x, warp = t >> 5, lane = t & 31;
  int wm = warp >> 2, wn = warp & 3;

  uint32_t sWb = (uint32_t)__cvta_generic_to_shared(sW);
  uint32_t sXb = (uint32_t)__cvta_generic_to_shared(sX);

  // one 32-row x 64-px chunk fill: exactly 1 cp16 per thread
  auto fill = [&](int buf, int pt, int kk) {
    int row = t >> 3, cg = t & 7;
    int kg = kk*32 + row;
    const __nv_bfloat16* src;
    if (DUAL) src = (kg < kC) ? (A.inA + ((size_t)b*kC + kg)*kHW)
                              : (A.inB + ((size_t)b*kC + (kg-kC))*kHW);
    else      src = A.inA + ((size_t)b*KDIM + kg)*kHW;
    cp16(sXb + (uint32_t)(buf*32*72 + row*72 + cg*8)*2, src + p0 + pt*64 + cg*8);
  };

  fill(0, 0, 0); cp_commit();
  // weights resident for the whole block (overlaps the async fill)
  for (int i = 8*t; i < COUT*KDIM; i += 2048) {
    int o = i / KDIM, k = i - o*KDIM;
    *(uint4*)&sW[o*KP + k] = *(const uint4*)(A.w + i);
  }

  float acc[MF][2][4];
#pragma unroll
  for (int i = 0; i < MF; i++)
#pragma unroll
    for (int j = 0; j < 2; j++)
#pragma unroll
      for (int k = 0; k < 4; k++) acc[i][j][k] = 0.f;

  for (int s = 0; s < NS; s++) {
    int pt = s / KCH, kk = s % KCH;
    if (s+1 < NS) { fill((s+1)&1, (s+1)/KCH, (s+1)%KCH); cp_commit(); cp_wait<1>(); }
    else          { cp_wait<0>(); }
    __syncthreads();
    uint32_t xbase = sXb + (uint32_t)((s&1)*32*72)*2;
#pragma unroll
    for (int ks = 0; ks < 2; ks++) {
      int wcol = kk*32 + ks*16 + (lane >> 4)*8;
      uint32_t a[MF][4];
#pragma unroll
      for (int mf = 0; mf < MF; mf++) {
        int row = wm*(COUT/2) + mf*16 + (lane & 15);
        ldsm4(a[mf], sWb + (uint32_t)(row*KP + wcol)*2);
      }
      uint32_t bf[4];
      {
        int xrow = ks*16 + ((lane >> 3) & 1)*8 + (lane & 7);
        int ncol = wn*16 + (lane >> 4)*8;
        ldsm4t(bf, xbase + (uint32_t)(xrow*72 + ncol)*2);
      }
#pragma unroll
      for (int mf = 0; mf < MF; mf++) {
        mma16816(acc[mf][0], a[mf], bf[0], bf[1]);
        mma16816(acc[mf][1], a[mf], bf[2], bf[3]);
      }
    }
    if (kk == KCH-1) {
      int px = p0 + pt*64;
#pragma unroll
      for (int mf = 0; mf < MF; mf++) {
        int row = wm*(COUT/2) + mf*16 + (lane >> 2);
        float bv0 = __ldg(&A.bias[row]);
        float bv1 = __ldg(&A.bias[row+8]);
#pragma unroll
        for (int nf = 0; nf < 2; nf++) {
          int col = wn*16 + nf*8 + (lane & 3)*2;
          size_t o0 = ((size_t)b*COUT + row)*kHW + px + col;
          size_t o1 = o0 + (size_t)8*kHW;
          if (RES) {
            float2 r0 = *(const float2*)(A.res + o0);
            float2 r1 = *(const float2*)(A.res + o1);
            *(float2*)(A.outF + o0) = make_float2(acc[mf][nf][0]+bv0+r0.x, acc[mf][nf][1]+bv0+r0.y);
            *(float2*)(A.outF + o1) = make_float2(acc[mf][nf][2]+bv1+r1.x, acc[mf][nf][3]+bv1+r1.y);
          } else {
            *(__nv_bfloat162*)(A.outB + o0) = pack_bf2(acc[mf][nf][0]+bv0, acc[mf][nf][1]+bv0);
            *(__nv_bfloat162*)(A.outB + o1) = pack_bf2(acc[mf][nf][2]+bv1, acc[mf][nf][3]+bv1);
          }
          acc[mf][nf][0] = acc[mf][nf][1] = acc[mf][nf][2] = acc[mf][nf][3] = 0.f;
        }
      }
    }
    __syncthreads();
  }
}

// ---------------- depthwise 3x3, tiled smem, all 5 branches in one launch ----------------
__global__ __launch_bounds__(256) void dwconv_kernel(
    DwArgs d0, DwArgs d1, DwArgs d2, DwArgs d3, DwArgs d4) {
  DwArgs a = d0;
  int z = blockIdx.z;
  if (z == 1) a = d1; else if (z == 2) a = d2; else if (z == 3) a = d3; else if (z == 4) a = d4;

  int bc = blockIdx.y;
  int c  = bc & (kNC-1);
  int h0 = blockIdx.x * 8;
  const __nv_bfloat16* ip = a.in + (size_t)bc*kHW;
  __nv_bfloat16* op = a.out + (size_t)bc*kHW;
  __shared__ __nv_bfloat16 tile[10][400];
  int t = threadIdx.x;

  for (int i = t; i < 160; i += 256) {
    int r = i >> 4, j = i & 15;
    tile[r][(j < 8) ? j : 384 + j] = __float2bfloat16(0.f);
  }
  for (int i = t; i < 480; i += 256) {
    int r = i / 48, cg = i - r*48;
    int h = h0 - 1 + r;
    uint4 v = make_uint4(0u, 0u, 0u, 0u);
    if (h >= 0 && h < kH) v = *(const uint4*)(ip + (size_t)h*kW + cg*8);
    *(uint4*)&tile[r][8 + cg*8] = v;
  }
  __syncthreads();

  float wr[9];
#pragma unroll
  for (int j = 0; j < 9; j++) wr[j] = __ldg(&a.w[c*9 + j]);
  float bv = __ldg(&a.bias[c]);

#pragma unroll
  for (int i = 0; i < 6; i++) {
    int p = 2*(t + 256*i);
    int row = p / 384, x = p - row*384;
    float a0 = bv, a1 = bv;
#pragma unroll
    for (int dy = 0; dy < 3; dy++)
#pragma unroll
      for (int dx = 0; dx < 3; dx++) {
        float wv = wr[dy*3 + dx];
        a0 += wv * __bfloat162float(tile[row+dy][7 + x + dx]);
        a1 += wv * __bfloat162float(tile[row+dy][8 + x + dx]);
      }
    *(__nv_bfloat162*)(op + (size_t)(h0+row)*kW + x) = pack_bf2(a0, a1);
  }
}

// ---------------- fused attention: O = softmax(Q K^T * scale) @ V ----------------
// Phase 1: Q(64x32)+K(192x32) chunks streamed via cp.async double-buffered ring;
// S(64x192) in regs -> softmax -> bf16 A into sA.
// Phase 2: O(64x384) in three 128-wide n-chunks; V double-buffered (overlays ring).
__global__ __launch_bounds__(128) void attn_kernel() {
  __shared__ __nv_bfloat16 sA[64*200];        // softmaxed A, stride 200
  __shared__ __nv_bfloat16 sBuf[2*256*40];    // ring: Q(64)+K(192) rows, stride 40; phase2 V ring
  int bc = blockIdx.y, side = blockIdx.z;
  const __nv_bfloat16* qb = g_Qm + (size_t)bc*kHW;
  const __nv_bfloat16* km = (side == 0 ? g_Kr : g_Kl) + (size_t)bc*kHW;
  const __nv_bfloat16* vb = (side == 0 ? g_Vl : g_Vr) + (size_t)bc*kHW;
  __nv_bfloat16* ob = (side == 0 ? g_Ol : g_Or) + (size_t)bc*kHW;
  int m0 = blockIdx.x * 64;
  int t = threadIdx.x, warp = t >> 5, lane = t & 31;

  uint32_t sAb = (uint32_t)__cvta_generic_to_shared(sA);
  uint32_t sBb = (uint32_t)__cvta_generic_to_shared(sBuf);

  // ---- phase 1 ----
  {
    // fill Q+K chunk kb into ring buffer buf (rows 0-63 = Q, 64-255 = K)
    auto fillQK = [&](int buf, int kb) {
      const __nv_bfloat16* qsrc = qb + (size_t)m0*kW + kb*32;
      const __nv_bfloat16* ksrc = km + kb*32;
      for (int i = t; i < 1024; i += 128) {
        int row = i >> 2, cg = i & 3;
        const __nv_bfloat16* src = (row < 64) ? (qsrc + (size_t)row*kW + cg*8)
                                              : (ksrc + (size_t)(row-64)*kW + cg*8);
        cp16(sBb + (uint32_t)(buf*10240 + row*40 + cg*8)*2, src);
      }
    };

    fillQK(0, 0); cp_commit();

    float acc[24][4];
#pragma unroll
    for (int i = 0; i < 24; i++)
#pragma unroll
      for (int j = 0; j < 4; j++) acc[i][j] = 0.f;

    for (int kb = 0; kb < 12; kb++) {          // 12 chunks of 32 k
      if (kb < 11) { fillQK((kb+1)&1, kb+1); cp_commit(); cp_wait<1>(); }
      else         { cp_wait<0>(); }
      __syncthreads();
      uint32_t qbase = sBb + (uint32_t)((kb&1)*10240)*2;
      uint32_t kbase = qbase + (uint32_t)(64*40)*2;
#pragma unroll
      for (int ks = 0; ks < 2; ks++) {
        int k0 = ks*16;
        uint32_t a[4];
        {
          int row = warp*16 + (lane & 15);
          int col = k0 + (lane >> 4)*8;
          ldsm4(a, qbase + (uint32_t)(row*40 + col)*2);
        }
        uint32_t bf[12][4];
#pragma unroll
        for (int nb = 0; nb < 12; nb++) {
          int nrow = nb*16 + (lane >> 4)*8 + (lane & 7);
          int col  = k0 + ((lane >> 3) & 1)*8;
          ldsm4(bf[nb], kbase + (uint32_t)(nrow*40 + col)*2);
        }
#pragma unroll
        for (int nf = 0; nf < 24; nf++)
          mma16816(acc[nf], a, bf[nf>>1][(nf&1)*2], bf[nf>>1][(nf&1)*2+1]);
      }
      __syncthreads();
    }

#pragma unroll
    for (int nf = 0; nf < 24; nf++)
#pragma unroll
      for (int j = 0; j < 4; j++) acc[nf][j] *= kScale;

    float mx0 = -1e30f, mx1 = -1e30f;
#pragma unroll
    for (int nf = 0; nf < 24; nf++) {
      mx0 = fmaxf(mx0, fmaxf(acc[nf][0], acc[nf][1]));
      mx1 = fmaxf(mx1, fmaxf(acc[nf][2], acc[nf][3]));
    }
#pragma unroll
    for (int o = 1; o <= 2; o <<= 1) {
      mx0 = fmaxf(mx0, __shfl_xor_sync(0xffffffffu, mx0, o));
      mx1 = fmaxf(mx1, __shfl_xor_sync(0xffffffffu, mx1, o));
    }
    float s0 = 0.f, s1 = 0.f;
#pragma unroll
    for (int nf = 0; nf < 24; nf++) {
      acc[nf][0] = __expf(acc[nf][0]-mx0); s0 += acc[nf][0];
      acc[nf][1] = __expf(acc[nf][1]-mx0); s0 += acc[nf][1];
      acc[nf][2] = __expf(acc[nf][2]-mx1); s1 += acc[nf][2];
      acc[nf][3] = __expf(acc[nf][3]-mx1); s1 += acc[nf][3];
    }
#pragma unroll
    for (int o = 1; o <= 2; o <<= 1) {
      s0 += __shfl_xor_sync(0xffffffffu, s0, o);
      s1 += __shfl_xor_sync(0xffffffffu, s1, o);
    }
    float i0 = 1.f/s0, i1 = 1.f/s1;

    int r0 = warp*16 + (lane >> 2);
#pragma unroll
    for (int nf = 0; nf < 24; nf++) {
      int c = nf*8 + (lane & 3)*2;
      *(__nv_bfloat162*)&sA[r0*200 + c]     = pack_bf2(acc[nf][0]*i0, acc[nf][1]*i0);
      *(__nv_bfloat162*)&sA[(r0+8)*200 + c] = pack_bf2(acc[nf][2]*i1, acc[nf][3]*i1);
    }
  }
  __syncthreads();

  // ---- phase 2: O = A @ V, warp grid 2x2, n-chunks of 128, V double-buffered ----
  int wm = warp >> 1, wn = warp & 1;
#pragma unroll
  for (int n0 = 0; n0 < kW; n0 += 128) {
    float oac[2][8][4];
#pragma unroll
    for (int i = 0; i < 2; i++)
#pragma unroll
      for (int j = 0; j < 8; j++)
#pragma unroll
        for (int k = 0; k < 4; k++) oac[i][j][k] = 0.f;

    for (int i = t; i < 512; i += 128) {
      int row = i >> 4, cg = i & 15;
      cp16(sBb + (uint32_t)(row*136 + cg*8)*2, vb + (size_t)row*kW + n0 + cg*8);
    }
    cp_commit();

    for (int kc = 0; kc < 6; kc++) {
      if (kc < 5) {
        uint32_t dst = sBb + (uint32_t)(((kc+1)&1)*32*136)*2;
        const __nv_bfloat16* vsrc = vb + (size_t)(kc+1)*32*kW + n0;
        for (int i = t; i < 512; i += 128) {
          int row = i >> 4, cg = i & 15;
          cp16(dst + (uint32_t)(row*136 + cg*8)*2, vsrc + (size_t)row*kW + cg*8);
        }
        cp_commit();
        cp_wait<1>();
      } else {
        cp_wait<0>();
      }
      __syncthreads();
      uint32_t vbase = sBb + (uint32_t)((kc&1)*32*136)*2;
#pragma unroll
      for (int ks = 0; ks < 2; ks++) {
        int k0 = ks*16;
        uint32_t a[2][4];
#pragma unroll
        for (int mf = 0; mf < 2; mf++) {
          int row = wm*32 + mf*16 + (lane & 15);
          int col = kc*32 + k0 + (lane >> 4)*8;
          ldsm4(a[mf], sAb + (uint32_t)(row*200 + col)*2);
        }
        uint32_t b[4][4];
#pragma unroll
        for (int nb = 0; nb < 4; nb++) {
          int krow = k0 + ((lane >> 3) & 1)*8 + (lane & 7);
          int ncol = wn*64 + nb*16 + (lane >> 4)*8;
          ldsm4t(b[nb], vbase + (uint32_t)(krow*136 + ncol)*2);
        }
#pragma unroll
        for (int mf = 0; mf < 2; mf++)
#pragma unroll
          for (int nf = 0; nf < 8; nf++)
            mma16816(oac[mf][nf], a[mf], b[nf>>1][(nf&1)*2], b[nf>>1][(nf&1)*2+1]);
      }
      __syncthreads();
    }
#pragma unroll
    for (int mf = 0; mf < 2; mf++)
#pragma unroll
      for (int nf = 0; nf < 8; nf++) {
        int r = m0 + wm*32 + mf*16 + (lane >> 2);
        int c = n0 + wn*64 + nf*8 + (lane & 3)*2;
        *(__nv_bfloat162*)(ob + (size_t)r*kW + c)     = pack_bf2(oac[mf][nf][0], oac[mf][nf][1]);
        *(__nv_bfloat162*)(ob + (size_t)(r+8)*kW + c) = pack_bf2(oac[mf][nf][2], oac[mf][nf][3]);
      }
  }
}

// ---------------- launch ----------------
extern "C" void kernel_launch(void* const* d_in, const int* in_sizes, int n_in,
                              void* d_out, int out_size) {
  const float* x_l   = (const float*)d_in[0];
  const float* x_r   = (const float*)d_in[1];
  const float* ln1_g = (const float*)d_in[2];
  const float* ln1_b = (const float*)d_in[3];
  const float* ln2_g = (const float*)d_in[4];
  const float* ln2_b = (const float*)d_in[5];
  const float* w1 = (const float*)d_in[6];   const float* b1 = (const float*)d_in[7];
  const float* w2 = (const float*)d_in[8];   const float* b2 = (const float*)d_in[9];
  const float* w3 = (const float*)d_in[10];  const float* b3 = (const float*)d_in[11];
  const float* w4 = (const float*)d_in[12];  const float* b4 = (const float*)d_in[13];
  const float* w5 = (const float*)d_in[14];  const float* b5 = (const float*)d_in[15];
  const float* dw1 = (const float*)d_in[16]; const float* db1 = (const float*)d_in[17];
  const float* dw2 = (const float*)d_in[18]; const float* db2 = (const float*)d_in[19];
  const float* dw3 = (const float*)d_in[20]; const float* db3 = (const float*)d_in[21];
  const float* dw4 = (const float*)d_in[22]; const float* db4 = (const float*)d_in[23];
  const float* dw5 = (const float*)d_in[24]; const float* db5 = (const float*)d_in[25];
  const float* w6 = (const float*)d_in[26];  const float* b6 = (const float*)d_in[27];
  const float* w7 = (const float*)d_in[28];  const float* b7 = (const float*)d_in[29];
  float* out = (float*)d_out;

  __nv_bfloat16 *nl, *nr, *P0, *P1, *P2, *P3, *P4, *Vl, *Kl, *Qm, *Kr, *Vr, *Ol, *Or, *Wbf;
  cudaGetSymbolAddress((void**)&nl, g_nl);
  cudaGetSymbolAddress((void**)&nr, g_nr);
  cudaGetSymbolAddress((void**)&P0, g_P0);
  cudaGetSymbolAddress((void**)&P1, g_P1);
  cudaGetSymbolAddress((void**)&P2, g_P2);
  cudaGetSymbolAddress((void**)&P3, g_P3);
  cudaGetSymbolAddress((void**)&P4, g_P4);
  cudaGetSymbolAddress((void**)&Vl, g_Vl);
  cudaGetSymbolAddress((void**)&Kl, g_Kl);
  cudaGetSymbolAddress((void**)&Qm, g_Qm);
  cudaGetSymbolAddress((void**)&Kr, g_Kr);
  cudaGetSymbolAddress((void**)&Vr, g_Vr);
  cudaGetSymbolAddress((void**)&Ol, g_Ol);
  cudaGetSymbolAddress((void**)&Or, g_Or);
  cudaGetSymbolAddress((void**)&Wbf, g_Wbf);

  // 0. weights -> bf16 arena
  wconv_kernel<<<256, 256>>>(w1, w2, w3, w4, w5, w6, w7);

  // 1. LayerNorm2d (both sides)
  ln_kernel<<<dim3(kB*kHW/256, 2), 256>>>(x_l, x_r, ln1_g, ln1_b, ln2_g, ln2_b, nl, nr);

  // 2. conv1x1 branches: four single-input branches in one launch, dual-input alone
  ConvArgs a1 = { nl, nullptr, Wbf,         b1, nullptr, nullptr, P0 };
  ConvArgs a2 = { nl, nullptr, Wbf + 8192,  b2, nullptr, nullptr, P1 };
  ConvArgs a3 = { nl, nr,      Wbf + 16384, b3, nullptr, nullptr, P2 };
  ConvArgs a4 = { nr, nullptr, Wbf + 32768, b4, nullptr, nullptr, P3 };
  ConvArgs a5 = { nr, nullptr, Wbf + 40960, b5, nullptr, nullptr, P4 };
  conv1x1_mma_kernel<kNC, kC, false, false><<<dim3(kHW/256, 4, kB), 256>>>(a1, a2, a4, a5);
  conv1x1_mma_kernel<kNC, 2*kC, true, false><<<dim3(kHW/256, 1, kB), 256>>>(a3, a3, a3, a3);

  // 3. all five depthwise 3x3 convs in one launch
  DwArgs dA = { P0, dw1, db1, Vl };
  DwArgs dB = { P1, dw2, db2, Kl };
  DwArgs dC = { P2, dw3, db3, Qm };
  DwArgs dD = { P3, dw4, db4, Kr };
  DwArgs dE = { P4, dw5, db5, Vr };
  dwconv_kernel<<<dim3(kH/8, kB*kNC, 5), 256>>>(dA, dB, dC, dD, dE);

  // 4. fused attention (S + softmax + O)
  attn_kernel<<<dim3(3, kB*kNC, 2), 128>>>();

  // 5. final conv1x1 + residual (both sides), fp32 out
  ConvArgs f0 = { Ol, nullptr, Wbf + 49152, b6, x_l, out, nullptr };
  ConvArgs f1 = { Or, nullptr, Wbf + 57344, b7, x_r, out + (size_t)kB*kC*kHW, nullptr };
  conv1x1_mma_kernel<kC, kNC, false, true><<<dim3(kHW/256, 2, kB), 256>>>(f0, f1, f0, f1);
}